// round 7
// baseline (speedup 1.0000x reference)
#include <cuda_runtime.h>
#include <cstdint>

#define BATCH 4
#define TFULL 2048
#define CDIM  1024
#define NHEAD 16
#define HDIM  64

// Scratch (allocation-free rule: __device__ globals)
__device__ float g_qkv[(size_t)BATCH * TFULL * 3 * CDIM];  // (B,T,3C) ~100.7 MB
__device__ float g_y[(size_t)BATCH * TFULL * CDIM];        // (B,T,C)  ~33.5 MB

__device__ __forceinline__ uint32_t f2tf32(float f) {
    uint32_t u;
    asm("cvt.rna.tf32.f32 %0, %1;" : "=r"(u) : "f"(f));
    return u;
}

#define MMA_TF32(d, a, b)                                                      \
    asm volatile(                                                              \
        "mma.sync.aligned.m16n8k8.row.col.f32.tf32.tf32.f32 "                  \
        "{%0,%1,%2,%3}, {%4,%5,%6,%7}, {%8,%9}, {%0,%1,%2,%3};"                \
        : "+f"(d[0]), "+f"(d[1]), "+f"(d[2]), "+f"(d[3])                       \
        : "r"(a.x), "r"(a.y), "r"(a.z), "r"(a.w), "r"(b.x), "r"(b.y))

// ---------------------------------------------------------------------------
// NT GEMM on tf32 tensor cores (unchanged from round 4, validated).
// ---------------------------------------------------------------------------
__global__ void __launch_bounds__(256) gemm_nt_tc(const float* __restrict__ A,
                                                  const float* __restrict__ B,
                                                  float* __restrict__ C,
                                                  int M, int N, int K)
{
    __shared__ uint32_t AF[8 * 2 * 32 * 4];
    __shared__ uint32_t BF[16 * 2 * 32 * 2];

    const int tid  = threadIdx.x;
    const int lane = tid & 31;
    const int warp = tid >> 5;
    const int wy = warp >> 2;
    const int wx = warp & 3;
    const int bm = blockIdx.y * 128;
    const int bn = blockIdx.x * 128;

    float acc[4][4][4];
#pragma unroll
    for (int i = 0; i < 4; ++i)
#pragma unroll
        for (int j = 0; j < 4; ++j)
#pragma unroll
            for (int r = 0; r < 4; ++r) acc[i][j][r] = 0.f;

    const int lrow0 = tid >> 2;
    const int lkk   = (tid & 3) * 4;

    float4 pa[2], pb[2];
#pragma unroll
    for (int l = 0; l < 2; ++l) {
        int row = lrow0 + l * 64;
        pa[l] = *(const float4*)(A + (size_t)(bm + row) * K + lkk);
        pb[l] = *(const float4*)(B + (size_t)(bn + row) * K + lkk);
    }

    for (int k0 = 0; k0 < K; k0 += 16) {
#pragma unroll
        for (int l = 0; l < 2; ++l) {
            int row = lrow0 + l * 64;
            const float va[4] = {pa[l].x, pa[l].y, pa[l].z, pa[l].w};
            const float vb[4] = {pb[l].x, pb[l].y, pb[l].z, pb[l].w};
            {
                int mt = row >> 4, r = row & 15;
                int ks = lkk >> 3;
                int chalf = (lkk & 7) >> 2;
                int reg = (r >> 3) + (chalf << 1);
                int base = ((mt * 2 + ks) * 32 + (r & 7) * 4) * 4 + reg;
#pragma unroll
                for (int j = 0; j < 4; ++j)
                    AF[base + j * 4] = f2tf32(va[j]);
            }
            {
                int nt = row >> 3, n = row & 7;
                int ks = lkk >> 3;
                int reg = (lkk & 7) >> 2;
                int base = ((nt * 2 + ks) * 32 + n * 4) * 2 + reg;
#pragma unroll
                for (int j = 0; j < 4; ++j)
                    BF[base + j * 2] = f2tf32(vb[j]);
            }
        }
        __syncthreads();

        if (k0 + 16 < K) {
#pragma unroll
            for (int l = 0; l < 2; ++l) {
                int row = lrow0 + l * 64;
                pa[l] = *(const float4*)(A + (size_t)(bm + row) * K + k0 + 16 + lkk);
                pb[l] = *(const float4*)(B + (size_t)(bn + row) * K + k0 + 16 + lkk);
            }
        }

#pragma unroll
        for (int ks = 0; ks < 2; ++ks) {
            uint4 a[4]; uint2 b[4];
#pragma unroll
            for (int mt = 0; mt < 4; ++mt) {
                int mtg = wy * 4 + mt;
                a[mt] = *(const uint4*)&AF[((mtg * 2 + ks) * 32 + lane) * 4];
            }
#pragma unroll
            for (int nt = 0; nt < 4; ++nt) {
                int ntg = wx * 4 + nt;
                b[nt] = *(const uint2*)&BF[((ntg * 2 + ks) * 32 + lane) * 2];
            }
#pragma unroll
            for (int mt = 0; mt < 4; ++mt)
#pragma unroll
                for (int nt = 0; nt < 4; ++nt)
                    MMA_TF32(acc[mt][nt], a[mt], b[nt]);
        }
        __syncthreads();
    }

#pragma unroll
    for (int mt = 0; mt < 4; ++mt) {
        int row0 = bm + wy * 64 + mt * 16 + (lane >> 2);
#pragma unroll
        for (int nt = 0; nt < 4; ++nt) {
            int col = bn + wx * 32 + nt * 8 + 2 * (lane & 3);
            *(float2*)(C + (size_t)row0 * N + col) =
                make_float2(acc[mt][nt][0], acc[mt][nt][1]);
            *(float2*)(C + (size_t)(row0 + 8) * N + col) =
                make_float2(acc[mt][nt][2], acc[mt][nt][3]);
        }
    }
}

// ---------------------------------------------------------------------------
// Causal flash attention on tf32 tensor cores with error-compensated
// 3-mma split (A*B ~= Ah*Bh + Ah*Br + Ar*Bh) for both QK^T and PV.
// Block = (b, h, 64-row q-tile), 8 warps; warp = m16 rows x 32-col half.
// Dynamic smem (u32 units):
//   QH[0:4096) QR[4096:8192)      Q fragments (A-layout), built once
//   KPH[8192:12288) KPR[...]      K fragments (B-layout), overwritten by P (A-layout)
//   VH[16384:20480) VR[...]       V^T fragments (B-layout)
//   smax[2][64], ssum[2][64]      cross-warp row stats
// ---------------------------------------------------------------------------
__global__ void __launch_bounds__(256) flash_attn_tc(const float* __restrict__ qkv,
                                                     float* __restrict__ y)
{
    extern __shared__ uint32_t dsm[];
    uint32_t* QH  = dsm;
    uint32_t* QR  = dsm + 4096;
    uint32_t* KPH = dsm + 8192;
    uint32_t* KPR = dsm + 12288;
    uint32_t* VH  = dsm + 16384;
    uint32_t* VR  = dsm + 20480;
    float* smax = (float*)(dsm + 24576);   // [2][64]
    float* ssum = smax + 128;              // [2][64]

    const int qt = (gridDim.x - 1) - blockIdx.x;
    const int bh = blockIdx.y;
    const int b = bh >> 4;
    const int h = bh & 15;
    const int q0 = qt * 64;
    const int tid  = threadIdx.x;
    const int lane = tid & 31;
    const int warp = tid >> 5;
    const int mt_w = warp >> 1;    // 0..3: rows [mt_w*16, +16)
    const int nh   = warp & 1;     // 0..1: col half [nh*32, +32)
    const size_t rs = 3 * CDIM;

    const float* qb = qkv + (size_t)b * TFULL * rs + (size_t)h * HDIM;
    const float* kb = qb + CDIM;
    const float* vb = qb + 2 * CDIM;

    // ---- build Q fragments (A-layout), scale 0.125 folded, hi+residual ----
#pragma unroll
    for (int l = 0; l < 4; ++l) {
        int i = tid + l * 256;
        int r = i >> 4;              // 0..63
        int d4 = (i & 15) * 4;       // 0..60
        float4 q = *(const float4*)(qb + (size_t)(q0 + r) * rs + d4);
        const float qv[4] = {q.x, q.y, q.z, q.w};
        int mt = r >> 4, m = r & 15;
#pragma unroll
        for (int j = 0; j < 4; ++j) {
            int d = d4 + j;
            int ks = d >> 3, c = d & 7;
            int idx = ((mt * 8 + ks) * 32 + (m & 7) * 4 + (c & 3)) * 4
                    + (m >> 3) + 2 * (c >> 2);
            float v = qv[j] * 0.125f;
            uint32_t hi = f2tf32(v);
            QH[idx] = hi;
            QR[idx] = f2tf32(v - __uint_as_float(hi));
        }
    }

    float m0 = -1e30f, m1 = -1e30f, l0 = 0.f, l1 = 0.f;
    float o[4][4];
#pragma unroll
    for (int nt = 0; nt < 4; ++nt)
#pragma unroll
        for (int r = 0; r < 4; ++r) o[nt][r] = 0.f;

    const int row0 = mt_w * 16 + (lane >> 2);
    const int row1 = row0 + 8;

    for (int kt = 0; kt <= qt; ++kt) {
        const int k0 = kt * 64;
        __syncthreads();   // prev-iter PV done; Q visible on first iter

        // ---- load K (B-layout) and V^T (B-layout), hi+residual ----
#pragma unroll
        for (int l = 0; l < 4; ++l) {
            int i = tid + l * 256;
            int r = i >> 4;
            int d4 = (i & 15) * 4;
            float4 kx = *(const float4*)(kb + (size_t)(k0 + r) * rs + d4);
            float4 vx = *(const float4*)(vb + (size_t)(k0 + r) * rs + d4);
            const float kv[4] = {kx.x, kx.y, kx.z, kx.w};
            const float vv[4] = {vx.x, vx.y, vx.z, vx.w};
#pragma unroll
            for (int j = 0; j < 4; ++j) {
                int d = d4 + j;
                {   // K: n = r (kv), k = d
                    int nt = r >> 3, n = r & 7, ks = d >> 3, kk = d & 7;
                    int idx = ((nt * 8 + ks) * 32 + n * 4 + (kk & 3)) * 2 + (kk >> 2);
                    uint32_t hi = f2tf32(kv[j]);
                    KPH[idx] = hi;
                    KPR[idx] = f2tf32(kv[j] - __uint_as_float(hi));
                }
                {   // V^T: n = d, k = r (kv)
                    int nt = d >> 3, ks = r >> 3, kk = r & 7;
                    int idx = ((nt * 8 + ks) * 32 + (d & 7) * 4 + (kk & 3)) * 2 + (kk >> 2);
                    uint32_t hi = f2tf32(vv[j]);
                    VH[idx] = hi;
                    VR[idx] = f2tf32(vv[j] - __uint_as_float(hi));
                }
            }
        }
        __syncthreads();

        // ---- S = Q K^T (split 3-mma) ----
        float s[4][4];
#pragma unroll
        for (int nt = 0; nt < 4; ++nt)
#pragma unroll
            for (int r = 0; r < 4; ++r) s[nt][r] = 0.f;

#pragma unroll
        for (int ks = 0; ks < 8; ++ks) {
            uint4 aH = ((const uint4*)QH)[(mt_w * 8 + ks) * 32 + lane];
            uint4 aR = ((const uint4*)QR)[(mt_w * 8 + ks) * 32 + lane];
#pragma unroll
            for (int nt = 0; nt < 4; ++nt) {
                int ntg = nh * 4 + nt;
                uint2 bH = ((const uint2*)KPH)[(ntg * 8 + ks) * 32 + lane];
                uint2 bR = ((const uint2*)KPR)[(ntg * 8 + ks) * 32 + lane];
                MMA_TF32(s[nt], aH, bH);
                MMA_TF32(s[nt], aH, bR);
                MMA_TF32(s[nt], aR, bH);
            }
        }

        // ---- causal mask on diagonal tile ----
        if (kt == qt) {
#pragma unroll
            for (int nt = 0; nt < 4; ++nt)
#pragma unroll
                for (int rg = 0; rg < 4; ++rg) {
                    int srow = mt_w * 16 + (lane >> 2) + 8 * (rg >> 1);
                    int scol = nh * 32 + nt * 8 + 2 * (lane & 3) + (rg & 1);
                    if (scol > srow) s[nt][rg] = -1e30f;
                }
        }

        // ---- row max: local -> quad shfl -> cross-warp via smem ----
        float pm0 = -1e30f, pm1 = -1e30f;
#pragma unroll
        for (int nt = 0; nt < 4; ++nt) {
            pm0 = fmaxf(pm0, fmaxf(s[nt][0], s[nt][1]));
            pm1 = fmaxf(pm1, fmaxf(s[nt][2], s[nt][3]));
        }
        pm0 = fmaxf(pm0, __shfl_xor_sync(0xffffffffu, pm0, 1));
        pm0 = fmaxf(pm0, __shfl_xor_sync(0xffffffffu, pm0, 2));
        pm1 = fmaxf(pm1, __shfl_xor_sync(0xffffffffu, pm1, 1));
        pm1 = fmaxf(pm1, __shfl_xor_sync(0xffffffffu, pm1, 2));
        if ((lane & 3) == 0) {
            smax[nh * 64 + row0] = pm0;
            smax[nh * 64 + row1] = pm1;
        }
        __syncthreads();   // also guarantees all warps finished reading K

        float mt0 = fmaxf(smax[row0], smax[64 + row0]);
        float mt1 = fmaxf(smax[row1], smax[64 + row1]);
        float mn0 = fmaxf(m0, mt0), mn1 = fmaxf(m1, mt1);
        float sc0 = __expf(m0 - mn0), sc1 = __expf(m1 - mn1);
        m0 = mn0; m1 = mn1;
        l0 *= sc0; l1 *= sc1;
#pragma unroll
        for (int nt = 0; nt < 4; ++nt) {
            o[nt][0] *= sc0; o[nt][1] *= sc0;
            o[nt][2] *= sc1; o[nt][3] *= sc1;
        }

        // ---- p = exp(s - m), write P fragments (A-layout into KP buffers) ----
        float ps0 = 0.f, ps1 = 0.f;
#pragma unroll
        for (int nt = 0; nt < 4; ++nt)
#pragma unroll
            for (int rg = 0; rg < 4; ++rg) {
                float mn = (rg < 2) ? mn0 : mn1;
                float p = __expf(s[nt][rg] - mn);
                if (rg < 2) ps0 += p; else ps1 += p;
                int m_ = (lane >> 2) + 8 * (rg >> 1);
                int scol = nh * 32 + nt * 8 + 2 * (lane & 3) + (rg & 1);
                int kk = scol & 7, ksp = scol >> 3;
                int idx = ((mt_w * 8 + ksp) * 32 + (m_ & 7) * 4 + (kk & 3)) * 4
                        + (m_ >> 3) + 2 * (kk >> 2);
                uint32_t hi = f2tf32(p);
                KPH[idx] = hi;
                KPR[idx] = f2tf32(p - __uint_as_float(hi));
            }
        ps0 += __shfl_xor_sync(0xffffffffu, ps0, 1);
        ps0 += __shfl_xor_sync(0xffffffffu, ps0, 2);
        ps1 += __shfl_xor_sync(0xffffffffu, ps1, 1);
        ps1 += __shfl_xor_sync(0xffffffffu, ps1, 2);
        if ((lane & 3) == 0) {
            ssum[nh * 64 + row0] = ps0;
            ssum[nh * 64 + row1] = ps1;
        }
        __syncthreads();   // P + sums visible

        l0 += ssum[row0] + ssum[64 + row0];
        l1 += ssum[row1] + ssum[64 + row1];

        // ---- O += P V (split 3-mma) ----
#pragma unroll
        for (int ks = 0; ks < 8; ++ks) {
            uint4 aH = ((const uint4*)KPH)[(mt_w * 8 + ks) * 32 + lane];
            uint4 aR = ((const uint4*)KPR)[(mt_w * 8 + ks) * 32 + lane];
#pragma unroll
            for (int nt = 0; nt < 4; ++nt) {
                int ntg = nh * 4 + nt;
                uint2 bH = ((const uint2*)VH)[(ntg * 8 + ks) * 32 + lane];
                uint2 bR = ((const uint2*)VR)[(ntg * 8 + ks) * 32 + lane];
                MMA_TF32(o[nt], aH, bH);
                MMA_TF32(o[nt], aH, bR);
                MMA_TF32(o[nt], aR, bH);
            }
        }
    }

    // ---- epilogue: O / l ----
    float inv0 = 1.f / l0, inv1 = 1.f / l1;
    float* yb = y + (size_t)b * TFULL * CDIM + (size_t)h * HDIM;
    int gr0 = q0 + row0;
#pragma unroll
    for (int nt = 0; nt < 4; ++nt) {
        int col = nh * 32 + nt * 8 + 2 * (lane & 3);
        *(float2*)(yb + (size_t)gr0 * CDIM + col) =
            make_float2(o[nt][0] * inv0, o[nt][1] * inv0);
        *(float2*)(yb + (size_t)(gr0 + 8) * CDIM + col) =
            make_float2(o[nt][2] * inv1, o[nt][3] * inv1);
    }
}

// ---------------------------------------------------------------------------
extern "C" void kernel_launch(void* const* d_in, const int* in_sizes, int n_in,
                              void* d_out, int out_size)
{
    const float* x      = (const float*)d_in[0];   // (B,T,C)
    const float* w_attn = (const float*)d_in[1];   // (3C,C)
    const float* w_proj = (const float*)d_in[2];   // (C,C)
    float* out = (float*)d_out;                    // (B,T,C)

    float* qkv = nullptr;
    float* yb  = nullptr;
    cudaGetSymbolAddress((void**)&qkv, g_qkv);
    cudaGetSymbolAddress((void**)&yb, g_y);

    const int M = BATCH * TFULL;          // 8192
    const int ATTN_SMEM = (24576 + 256) * 4;   // 99328 bytes

    cudaFuncSetAttribute(flash_attn_tc,
                         cudaFuncAttributeMaxDynamicSharedMemorySize, ATTN_SMEM);

    // 1) qkv = x @ w_attn^T   : (8192 x 3072)
    gemm_nt_tc<<<dim3(3 * CDIM / 128, M / 128), 256>>>(x, w_attn, qkv, M, 3 * CDIM, CDIM);

    // 2) y = causal_attention(qkv)
    flash_attn_tc<<<dim3(TFULL / 64, BATCH * NHEAD), 256, ATTN_SMEM>>>(qkv, yb);

    // 3) out = y @ w_proj^T   : (8192 x 1024)
    gemm_nt_tc<<<dim3(CDIM / 128, M / 128), 256>>>(yb, w_proj, out, M, CDIM, CDIM);
}

// round 9
// speedup vs baseline: 1.2266x; 1.2266x over previous
#include <cuda_runtime.h>
#include <cstdint>

#define BATCH 4
#define TFULL 2048
#define CDIM  1024
#define NHEAD 16
#define HDIM  64

// Scratch (allocation-free rule: __device__ globals)
__device__ float g_qkv[(size_t)BATCH * TFULL * 3 * CDIM];  // (B,T,3C) ~100.7 MB
__device__ float g_y[(size_t)BATCH * TFULL * CDIM];        // (B,T,C)  ~33.5 MB

__device__ __forceinline__ uint32_t f2tf32(float f) {
    uint32_t u;
    asm("cvt.rna.tf32.f32 %0, %1;" : "=r"(u) : "f"(f));
    return u;
}

#define MMA_TF32(d, a, b)                                                      \
    asm volatile(                                                              \
        "mma.sync.aligned.m16n8k8.row.col.f32.tf32.tf32.f32 "                  \
        "{%0,%1,%2,%3}, {%4,%5,%6,%7}, {%8,%9}, {%0,%1,%2,%3};"                \
        : "+f"(d[0]), "+f"(d[1]), "+f"(d[2]), "+f"(d[3])                       \
        : "r"(a.x), "r"(a.y), "r"(a.z), "r"(a.w), "r"(b.x), "r"(b.y))

// ---------------------------------------------------------------------------
// NT GEMM on tf32 tensor cores, double-buffered smem software pipeline.
// C[m,n] = sum_k A[m,k]*B[n,k]. 128x128 tile, k-chunk 16, 8 warps 64x32 each.
// Per iter: store chunk i+1 -> buf[(i+1)&1]; LDG chunk i+2; compute buf[i&1];
// one __syncthreads per chunk. STS+cvt (fma/alu) overlap mma (tensor).
// ---------------------------------------------------------------------------
__global__ void __launch_bounds__(256, 2) gemm_nt_tc(const float* __restrict__ A,
                                                     const float* __restrict__ B,
                                                     float* __restrict__ C,
                                                     int M, int N, int K)
{
    __shared__ uint32_t AF[2][8 * 2 * 32 * 4];   // 2 x 8 KB
    __shared__ uint32_t BF[2][16 * 2 * 32 * 2];  // 2 x 8 KB

    const int tid  = threadIdx.x;
    const int lane = tid & 31;
    const int warp = tid >> 5;
    const int wy = warp >> 2;
    const int wx = warp & 3;
    const int bm = blockIdx.y * 128;
    const int bn = blockIdx.x * 128;

    float acc[4][4][4];
#pragma unroll
    for (int i = 0; i < 4; ++i)
#pragma unroll
        for (int j = 0; j < 4; ++j)
#pragma unroll
            for (int r = 0; r < 4; ++r) acc[i][j][r] = 0.f;

    const int lrow0 = tid >> 2;          // 0..63
    const int lkk   = (tid & 3) * 4;     // 0,4,8,12

    // Precomputed fragment-store bases (validated layout from round 4)
    int abase[2], bbase[2];
#pragma unroll
    for (int l = 0; l < 2; ++l) {
        int row = lrow0 + l * 64;
        {
            int mt = row >> 4, r = row & 15;
            int ks = lkk >> 3;
            int chalf = (lkk & 7) >> 2;
            int reg = (r >> 3) + (chalf << 1);
            abase[l] = ((mt * 2 + ks) * 32 + (r & 7) * 4) * 4 + reg;
        }
        {
            int nt = row >> 3, n = row & 7;
            int ks = lkk >> 3;
            int reg = (lkk & 7) >> 2;
            bbase[l] = ((nt * 2 + ks) * 32 + n * 4) * 2 + reg;
        }
    }

    float4 pa[2], pb[2];

    auto load_chunk = [&](int k0) {
#pragma unroll
        for (int l = 0; l < 2; ++l) {
            int row = lrow0 + l * 64;
            pa[l] = *(const float4*)(A + (size_t)(bm + row) * K + k0 + lkk);
            pb[l] = *(const float4*)(B + (size_t)(bn + row) * K + k0 + lkk);
        }
    };
    auto store_chunk = [&](int buf) {
#pragma unroll
        for (int l = 0; l < 2; ++l) {
            const float va[4] = {pa[l].x, pa[l].y, pa[l].z, pa[l].w};
            const float vb[4] = {pb[l].x, pb[l].y, pb[l].z, pb[l].w};
#pragma unroll
            for (int j = 0; j < 4; ++j) {
                AF[buf][abase[l] + j * 4] = f2tf32(va[j]);
                BF[buf][bbase[l] + j * 2] = f2tf32(vb[j]);
            }
        }
    };

    const int NCH = K >> 4;   // chunks of 16

    // Prologue: chunk 0 -> buf 0; chunk 1 -> regs
    load_chunk(0);
    store_chunk(0);
    __syncthreads();
    load_chunk(16);

    for (int i = 0; i < NCH; ++i) {
        const int cur = i & 1;
        if (i + 1 < NCH) store_chunk(1 - cur);      // regs hold chunk i+1
        if (i + 2 < NCH) load_chunk((i + 2) << 4);  // refill regs (after store)

#pragma unroll
        for (int ks = 0; ks < 2; ++ks) {
            uint4 a[4]; uint2 b[4];
#pragma unroll
            for (int mt = 0; mt < 4; ++mt) {
                int mtg = wy * 4 + mt;
                a[mt] = *(const uint4*)&AF[cur][((mtg * 2 + ks) * 32 + lane) * 4];
            }
#pragma unroll
            for (int nt = 0; nt < 4; ++nt) {
                int ntg = wx * 4 + nt;
                b[nt] = *(const uint2*)&BF[cur][((ntg * 2 + ks) * 32 + lane) * 2];
            }
#pragma unroll
            for (int mt = 0; mt < 4; ++mt)
#pragma unroll
                for (int nt = 0; nt < 4; ++nt)
                    MMA_TF32(acc[mt][nt], a[mt], b[nt]);
        }
        __syncthreads();   // compute(i) done; stores of i+1 visible
    }

#pragma unroll
    for (int mt = 0; mt < 4; ++mt) {
        int row0 = bm + wy * 64 + mt * 16 + (lane >> 2);
#pragma unroll
        for (int nt = 0; nt < 4; ++nt) {
            int col = bn + wx * 32 + nt * 8 + 2 * (lane & 3);
            *(float2*)(C + (size_t)row0 * N + col) =
                make_float2(acc[mt][nt][0], acc[mt][nt][1]);
            *(float2*)(C + (size_t)(row0 + 8) * N + col) =
                make_float2(acc[mt][nt][2], acc[mt][nt][3]);
        }
    }
}

// ---------------------------------------------------------------------------
// Causal flash attention, fp32 SIMT (validated round-3/4 version, ~1170us).
// ---------------------------------------------------------------------------
__global__ void __launch_bounds__(256) flash_attn(const float* __restrict__ qkv,
                                                  float* __restrict__ y)
{
    __shared__ float Qt[64 * 64];   // Q^T, swizzled: Qt[d*64 + (r ^ (d&60))]
    __shared__ float KPt[64 * 64];  // K^T (swizzled), then P^T (swizzled)
    __shared__ float Vs[64 * 64];   // V row-major

    const int qt = (gridDim.x - 1) - blockIdx.x;
    const int bh = blockIdx.y;
    const int b = bh >> 4;
    const int h = bh & 15;
    const int q0 = qt * 64;
    const int tid = threadIdx.x;
    const int tx = tid & 15;
    const int ty = tid >> 4;
    const size_t rs = 3 * CDIM;

    const float* qb = qkv + (size_t)b * TFULL * rs + (size_t)h * HDIM;
    const float* kb = qb + CDIM;
    const float* vb = qb + 2 * CDIM;

#pragma unroll
    for (int l = 0; l < 4; ++l) {
        int i = tid + l * 256;
        int r = i >> 4;
        int d4 = (i & 15) * 4;
        float4 q = *(const float4*)(qb + (size_t)(q0 + r) * rs + d4);
        Qt[(d4 + 0) * 64 + (r ^ ((d4 + 0) & 60))] = q.x * 0.125f;
        Qt[(d4 + 1) * 64 + (r ^ ((d4 + 1) & 60))] = q.y * 0.125f;
        Qt[(d4 + 2) * 64 + (r ^ ((d4 + 2) & 60))] = q.z * 0.125f;
        Qt[(d4 + 3) * 64 + (r ^ ((d4 + 3) & 60))] = q.w * 0.125f;
    }

    float m_i[4], l_i[4], o[4][4];
#pragma unroll
    for (int i = 0; i < 4; ++i) {
        m_i[i] = -1e30f;
        l_i[i] = 0.f;
#pragma unroll
        for (int j = 0; j < 4; ++j) o[i][j] = 0.f;
    }

    for (int kt = 0; kt <= qt; ++kt) {
        const int k0 = kt * 64;
        __syncthreads();

#pragma unroll
        for (int l = 0; l < 4; ++l) {
            int i = tid + l * 256;
            int r = i >> 4;
            int d4 = (i & 15) * 4;
            float4 kx = *(const float4*)(kb + (size_t)(k0 + r) * rs + d4);
            KPt[(d4 + 0) * 64 + (r ^ ((d4 + 0) & 60))] = kx.x;
            KPt[(d4 + 1) * 64 + (r ^ ((d4 + 1) & 60))] = kx.y;
            KPt[(d4 + 2) * 64 + (r ^ ((d4 + 2) & 60))] = kx.z;
            KPt[(d4 + 3) * 64 + (r ^ ((d4 + 3) & 60))] = kx.w;
            float4 vx = *(const float4*)(vb + (size_t)(k0 + r) * rs + d4);
            *(float4*)&Vs[r * 64 + d4] = vx;
        }
        __syncthreads();

        float s[4][4];
#pragma unroll
        for (int i = 0; i < 4; ++i)
#pragma unroll
            for (int j = 0; j < 4; ++j) s[i][j] = 0.f;

#pragma unroll 16
        for (int d = 0; d < 64; ++d) {
            float4 qv = *(const float4*)&Qt[d * 64 + ((ty * 4) ^ (d & 60))];
            float4 kv = *(const float4*)&KPt[d * 64 + ((tx * 4) ^ (d & 60))];
            s[0][0] += qv.x * kv.x; s[0][1] += qv.x * kv.y; s[0][2] += qv.x * kv.z; s[0][3] += qv.x * kv.w;
            s[1][0] += qv.y * kv.x; s[1][1] += qv.y * kv.y; s[1][2] += qv.y * kv.z; s[1][3] += qv.y * kv.w;
            s[2][0] += qv.z * kv.x; s[2][1] += qv.z * kv.y; s[2][2] += qv.z * kv.z; s[2][3] += qv.z * kv.w;
            s[3][0] += qv.w * kv.x; s[3][1] += qv.w * kv.y; s[3][2] += qv.w * kv.z; s[3][3] += qv.w * kv.w;
        }

        if (kt == qt) {
#pragma unroll
            for (int i = 0; i < 4; ++i)
#pragma unroll
                for (int j = 0; j < 4; ++j)
                    if (tx * 4 + j > ty * 4 + i) s[i][j] = -1e30f;
        }

        float mt[4], ls[4];
#pragma unroll
        for (int i = 0; i < 4; ++i)
            mt[i] = fmaxf(fmaxf(s[i][0], s[i][1]), fmaxf(s[i][2], s[i][3]));
#pragma unroll
        for (int off = 1; off < 16; off <<= 1)
#pragma unroll
            for (int i = 0; i < 4; ++i)
                mt[i] = fmaxf(mt[i], __shfl_xor_sync(0xffffffffu, mt[i], off));

#pragma unroll
        for (int i = 0; i < 4; ++i) {
            float mn = fmaxf(m_i[i], mt[i]);
            float sc = __expf(m_i[i] - mn);
            m_i[i] = mn;
            l_i[i] *= sc;
#pragma unroll
            for (int j = 0; j < 4; ++j) o[i][j] *= sc;
            float lsum = 0.f;
#pragma unroll
            for (int j = 0; j < 4; ++j) {
                float p = __expf(s[i][j] - mn);
                s[i][j] = p;
                lsum += p;
            }
            ls[i] = lsum;
        }
#pragma unroll
        for (int off = 1; off < 16; off <<= 1)
#pragma unroll
            for (int i = 0; i < 4; ++i)
                ls[i] += __shfl_xor_sync(0xffffffffu, ls[i], off);
#pragma unroll
        for (int i = 0; i < 4; ++i) l_i[i] += ls[i];

        __syncthreads();
#pragma unroll
        for (int j = 0; j < 4; ++j) {
            int n = tx * 4 + j;
#pragma unroll
            for (int i = 0; i < 4; ++i)
                KPt[n * 64 + ((ty * 4 + i) ^ (n & 60))] = s[i][j];
        }
        __syncthreads();

#pragma unroll 16
        for (int k = 0; k < 64; ++k) {
            float4 pv = *(const float4*)&KPt[k * 64 + ((ty * 4) ^ (k & 60))];
            float4 vv = *(const float4*)&Vs[k * 64 + tx * 4];
            o[0][0] += pv.x * vv.x; o[0][1] += pv.x * vv.y; o[0][2] += pv.x * vv.z; o[0][3] += pv.x * vv.w;
            o[1][0] += pv.y * vv.x; o[1][1] += pv.y * vv.y; o[1][2] += pv.y * vv.z; o[1][3] += pv.y * vv.w;
            o[2][0] += pv.z * vv.x; o[2][1] += pv.z * vv.y; o[2][2] += pv.z * vv.z; o[2][3] += pv.z * vv.w;
            o[3][0] += pv.w * vv.x; o[3][1] += pv.w * vv.y; o[3][2] += pv.w * vv.z; o[3][3] += pv.w * vv.w;
        }
    }

    float* yb = y + (size_t)b * TFULL * CDIM + (size_t)h * HDIM;
#pragma unroll
    for (int i = 0; i < 4; ++i) {
        int r = q0 + ty * 4 + i;
        float inv = 1.f / l_i[i];
        *(float4*)(yb + (size_t)r * CDIM + tx * 4) =
            make_float4(o[i][0] * inv, o[i][1] * inv, o[i][2] * inv, o[i][3] * inv);
    }
}

// ---------------------------------------------------------------------------
extern "C" void kernel_launch(void* const* d_in, const int* in_sizes, int n_in,
                              void* d_out, int out_size)
{
    const float* x      = (const float*)d_in[0];   // (B,T,C)
    const float* w_attn = (const float*)d_in[1];   // (3C,C)
    const float* w_proj = (const float*)d_in[2];   // (C,C)
    float* out = (float*)d_out;                    // (B,T,C)

    float* qkv = nullptr;
    float* yb  = nullptr;
    cudaGetSymbolAddress((void**)&qkv, g_qkv);
    cudaGetSymbolAddress((void**)&yb, g_y);

    const int M = BATCH * TFULL;          // 8192

    // 1) qkv = x @ w_attn^T   : (8192 x 3072)
    gemm_nt_tc<<<dim3(3 * CDIM / 128, M / 128), 256>>>(x, w_attn, qkv, M, 3 * CDIM, CDIM);

    // 2) y = causal_attention(qkv)
    flash_attn<<<dim3(TFULL / 64, BATCH * NHEAD), 256>>>(qkv, yb);

    // 3) out = y @ w_proj^T   : (8192 x 1024)
    gemm_nt_tc<<<dim3(CDIM / 128, M / 128), 256>>>(yb, w_proj, out, M, CDIM, CDIM);
}

// round 10
// speedup vs baseline: 1.2380x; 1.0093x over previous
#include <cuda_runtime.h>
#include <cstdint>

#define BATCH 4
#define TFULL 2048
#define CDIM  1024
#define NHEAD 16
#define HDIM  64

// Scratch (allocation-free rule: __device__ globals)
__device__ float g_qkv[(size_t)BATCH * TFULL * 3 * CDIM];  // (B,T,3C) ~100.7 MB
__device__ float g_y[(size_t)BATCH * TFULL * CDIM];        // (B,T,C)  ~33.5 MB

__device__ __forceinline__ uint32_t f2tf32(float f) {
    uint32_t u;
    asm("cvt.rna.tf32.f32 %0, %1;" : "=r"(u) : "f"(f));
    return u;
}

#define MMA_TF32(d, a, b)                                                      \
    asm volatile(                                                              \
        "mma.sync.aligned.m16n8k8.row.col.f32.tf32.tf32.f32 "                  \
        "{%0,%1,%2,%3}, {%4,%5,%6,%7}, {%8,%9}, {%0,%1,%2,%3};"                \
        : "+f"(d[0]), "+f"(d[1]), "+f"(d[2]), "+f"(d[3])                       \
        : "r"(a.x), "r"(a.y), "r"(a.z), "r"(a.w), "r"(b.x), "r"(b.y))

// ---------------------------------------------------------------------------
// NT GEMM on tf32 tensor cores, double-buffered smem software pipeline.
// C[m,n] = sum_k A[m,k]*B[n,k]. 128x128 tile, k-chunk 16, 8 warps 64x32 each.
// Per iter: store chunk i+1 -> buf[(i+1)&1]; LDG chunk i+2; compute buf[i&1];
// one __syncthreads per chunk. STS+cvt (fma/alu) overlap mma (tensor).
// ---------------------------------------------------------------------------
__global__ void __launch_bounds__(256, 2) gemm_nt_tc(const float* __restrict__ A,
                                                     const float* __restrict__ B,
                                                     float* __restrict__ C,
                                                     int M, int N, int K)
{
    __shared__ uint32_t AF[2][8 * 2 * 32 * 4];   // 2 x 8 KB
    __shared__ uint32_t BF[2][16 * 2 * 32 * 2];  // 2 x 8 KB

    const int tid  = threadIdx.x;
    const int lane = tid & 31;
    const int warp = tid >> 5;
    const int wy = warp >> 2;
    const int wx = warp & 3;
    const int bm = blockIdx.y * 128;
    const int bn = blockIdx.x * 128;

    float acc[4][4][4];
#pragma unroll
    for (int i = 0; i < 4; ++i)
#pragma unroll
        for (int j = 0; j < 4; ++j)
#pragma unroll
            for (int r = 0; r < 4; ++r) acc[i][j][r] = 0.f;

    const int lrow0 = tid >> 2;          // 0..63
    const int lkk   = (tid & 3) * 4;     // 0,4,8,12

    // Precomputed fragment-store bases (validated layout from round 4)
    int abase[2], bbase[2];
#pragma unroll
    for (int l = 0; l < 2; ++l) {
        int row = lrow0 + l * 64;
        {
            int mt = row >> 4, r = row & 15;
            int ks = lkk >> 3;
            int chalf = (lkk & 7) >> 2;
            int reg = (r >> 3) + (chalf << 1);
            abase[l] = ((mt * 2 + ks) * 32 + (r & 7) * 4) * 4 + reg;
        }
        {
            int nt = row >> 3, n = row & 7;
            int ks = lkk >> 3;
            int reg = (lkk & 7) >> 2;
            bbase[l] = ((nt * 2 + ks) * 32 + n * 4) * 2 + reg;
        }
    }

    float4 pa[2], pb[2];

    auto load_chunk = [&](int k0) {
#pragma unroll
        for (int l = 0; l < 2; ++l) {
            int row = lrow0 + l * 64;
            pa[l] = *(const float4*)(A + (size_t)(bm + row) * K + k0 + lkk);
            pb[l] = *(const float4*)(B + (size_t)(bn + row) * K + k0 + lkk);
        }
    };
    auto store_chunk = [&](int buf) {
#pragma unroll
        for (int l = 0; l < 2; ++l) {
            const float va[4] = {pa[l].x, pa[l].y, pa[l].z, pa[l].w};
            const float vb[4] = {pb[l].x, pb[l].y, pb[l].z, pb[l].w};
#pragma unroll
            for (int j = 0; j < 4; ++j) {
                AF[buf][abase[l] + j * 4] = f2tf32(va[j]);
                BF[buf][bbase[l] + j * 2] = f2tf32(vb[j]);
            }
        }
    };

    const int NCH = K >> 4;   // chunks of 16

    // Prologue: chunk 0 -> buf 0; chunk 1 -> regs
    load_chunk(0);
    store_chunk(0);
    __syncthreads();
    load_chunk(16);

    for (int i = 0; i < NCH; ++i) {
        const int cur = i & 1;
        if (i + 1 < NCH) store_chunk(1 - cur);      // regs hold chunk i+1
        if (i + 2 < NCH) load_chunk((i + 2) << 4);  // refill regs (after store)

#pragma unroll
        for (int ks = 0; ks < 2; ++ks) {
            uint4 a[4]; uint2 b[4];
#pragma unroll
            for (int mt = 0; mt < 4; ++mt) {
                int mtg = wy * 4 + mt;
                a[mt] = *(const uint4*)&AF[cur][((mtg * 2 + ks) * 32 + lane) * 4];
            }
#pragma unroll
            for (int nt = 0; nt < 4; ++nt) {
                int ntg = wx * 4 + nt;
                b[nt] = *(const uint2*)&BF[cur][((ntg * 2 + ks) * 32 + lane) * 2];
            }
#pragma unroll
            for (int mt = 0; mt < 4; ++mt)
#pragma unroll
                for (int nt = 0; nt < 4; ++nt)
                    MMA_TF32(acc[mt][nt], a[mt], b[nt]);
        }
        __syncthreads();   // compute(i) done; stores of i+1 visible
    }

#pragma unroll
    for (int mt = 0; mt < 4; ++mt) {
        int row0 = bm + wy * 64 + mt * 16 + (lane >> 2);
#pragma unroll
        for (int nt = 0; nt < 4; ++nt) {
            int col = bn + wx * 32 + nt * 8 + 2 * (lane & 3);
            *(float2*)(C + (size_t)row0 * N + col) =
                make_float2(acc[mt][nt][0], acc[mt][nt][1]);
            *(float2*)(C + (size_t)(row0 + 8) * N + col) =
                make_float2(acc[mt][nt][2], acc[mt][nt][3]);
        }
    }
}

// ---------------------------------------------------------------------------
// Causal flash attention, fp32 SIMT (validated round-3/4 version, ~1170us).
// ---------------------------------------------------------------------------
__global__ void __launch_bounds__(256) flash_attn(const float* __restrict__ qkv,
                                                  float* __restrict__ y)
{
    __shared__ float Qt[64 * 64];   // Q^T, swizzled: Qt[d*64 + (r ^ (d&60))]
    __shared__ float KPt[64 * 64];  // K^T (swizzled), then P^T (swizzled)
    __shared__ float Vs[64 * 64];   // V row-major

    const int qt = (gridDim.x - 1) - blockIdx.x;
    const int bh = blockIdx.y;
    const int b = bh >> 4;
    const int h = bh & 15;
    const int q0 = qt * 64;
    const int tid = threadIdx.x;
    const int tx = tid & 15;
    const int ty = tid >> 4;
    const size_t rs = 3 * CDIM;

    const float* qb = qkv + (size_t)b * TFULL * rs + (size_t)h * HDIM;
    const float* kb = qb + CDIM;
    const float* vb = qb + 2 * CDIM;

#pragma unroll
    for (int l = 0; l < 4; ++l) {
        int i = tid + l * 256;
        int r = i >> 4;
        int d4 = (i & 15) * 4;
        float4 q = *(const float4*)(qb + (size_t)(q0 + r) * rs + d4);
        Qt[(d4 + 0) * 64 + (r ^ ((d4 + 0) & 60))] = q.x * 0.125f;
        Qt[(d4 + 1) * 64 + (r ^ ((d4 + 1) & 60))] = q.y * 0.125f;
        Qt[(d4 + 2) * 64 + (r ^ ((d4 + 2) & 60))] = q.z * 0.125f;
        Qt[(d4 + 3) * 64 + (r ^ ((d4 + 3) & 60))] = q.w * 0.125f;
    }

    float m_i[4], l_i[4], o[4][4];
#pragma unroll
    for (int i = 0; i < 4; ++i) {
        m_i[i] = -1e30f;
        l_i[i] = 0.f;
#pragma unroll
        for (int j = 0; j < 4; ++j) o[i][j] = 0.f;
    }

    for (int kt = 0; kt <= qt; ++kt) {
        const int k0 = kt * 64;
        __syncthreads();

#pragma unroll
        for (int l = 0; l < 4; ++l) {
            int i = tid + l * 256;
            int r = i >> 4;
            int d4 = (i & 15) * 4;
            float4 kx = *(const float4*)(kb + (size_t)(k0 + r) * rs + d4);
            KPt[(d4 + 0) * 64 + (r ^ ((d4 + 0) & 60))] = kx.x;
            KPt[(d4 + 1) * 64 + (r ^ ((d4 + 1) & 60))] = kx.y;
            KPt[(d4 + 2) * 64 + (r ^ ((d4 + 2) & 60))] = kx.z;
            KPt[(d4 + 3) * 64 + (r ^ ((d4 + 3) & 60))] = kx.w;
            float4 vx = *(const float4*)(vb + (size_t)(k0 + r) * rs + d4);
            *(float4*)&Vs[r * 64 + d4] = vx;
        }
        __syncthreads();

        float s[4][4];
#pragma unroll
        for (int i = 0; i < 4; ++i)
#pragma unroll
            for (int j = 0; j < 4; ++j) s[i][j] = 0.f;

#pragma unroll 16
        for (int d = 0; d < 64; ++d) {
            float4 qv = *(const float4*)&Qt[d * 64 + ((ty * 4) ^ (d & 60))];
            float4 kv = *(const float4*)&KPt[d * 64 + ((tx * 4) ^ (d & 60))];
            s[0][0] += qv.x * kv.x; s[0][1] += qv.x * kv.y; s[0][2] += qv.x * kv.z; s[0][3] += qv.x * kv.w;
            s[1][0] += qv.y * kv.x; s[1][1] += qv.y * kv.y; s[1][2] += qv.y * kv.z; s[1][3] += qv.y * kv.w;
            s[2][0] += qv.z * kv.x; s[2][1] += qv.z * kv.y; s[2][2] += qv.z * kv.z; s[2][3] += qv.z * kv.w;
            s[3][0] += qv.w * kv.x; s[3][1] += qv.w * kv.y; s[3][2] += qv.w * kv.z; s[3][3] += qv.w * kv.w;
        }

        if (kt == qt) {
#pragma unroll
            for (int i = 0; i < 4; ++i)
#pragma unroll
                for (int j = 0; j < 4; ++j)
                    if (tx * 4 + j > ty * 4 + i) s[i][j] = -1e30f;
        }

        float mt[4], ls[4];
#pragma unroll
        for (int i = 0; i < 4; ++i)
            mt[i] = fmaxf(fmaxf(s[i][0], s[i][1]), fmaxf(s[i][2], s[i][3]));
#pragma unroll
        for (int off = 1; off < 16; off <<= 1)
#pragma unroll
            for (int i = 0; i < 4; ++i)
                mt[i] = fmaxf(mt[i], __shfl_xor_sync(0xffffffffu, mt[i], off));

#pragma unroll
        for (int i = 0; i < 4; ++i) {
            float mn = fmaxf(m_i[i], mt[i]);
            float sc = __expf(m_i[i] - mn);
            m_i[i] = mn;
            l_i[i] *= sc;
#pragma unroll
            for (int j = 0; j < 4; ++j) o[i][j] *= sc;
            float lsum = 0.f;
#pragma unroll
            for (int j = 0; j < 4; ++j) {
                float p = __expf(s[i][j] - mn);
                s[i][j] = p;
                lsum += p;
            }
            ls[i] = lsum;
        }
#pragma unroll
        for (int off = 1; off < 16; off <<= 1)
#pragma unroll
            for (int i = 0; i < 4; ++i)
                ls[i] += __shfl_xor_sync(0xffffffffu, ls[i], off);
#pragma unroll
        for (int i = 0; i < 4; ++i) l_i[i] += ls[i];

        __syncthreads();
#pragma unroll
        for (int j = 0; j < 4; ++j) {
            int n = tx * 4 + j;
#pragma unroll
            for (int i = 0; i < 4; ++i)
                KPt[n * 64 + ((ty * 4 + i) ^ (n & 60))] = s[i][j];
        }
        __syncthreads();

#pragma unroll 16
        for (int k = 0; k < 64; ++k) {
            float4 pv = *(const float4*)&KPt[k * 64 + ((ty * 4) ^ (k & 60))];
            float4 vv = *(const float4*)&Vs[k * 64 + tx * 4];
            o[0][0] += pv.x * vv.x; o[0][1] += pv.x * vv.y; o[0][2] += pv.x * vv.z; o[0][3] += pv.x * vv.w;
            o[1][0] += pv.y * vv.x; o[1][1] += pv.y * vv.y; o[1][2] += pv.y * vv.z; o[1][3] += pv.y * vv.w;
            o[2][0] += pv.z * vv.x; o[2][1] += pv.z * vv.y; o[2][2] += pv.z * vv.z; o[2][3] += pv.z * vv.w;
            o[3][0] += pv.w * vv.x; o[3][1] += pv.w * vv.y; o[3][2] += pv.w * vv.z; o[3][3] += pv.w * vv.w;
        }
    }

    float* yb = y + (size_t)b * TFULL * CDIM + (size_t)h * HDIM;
#pragma unroll
    for (int i = 0; i < 4; ++i) {
        int r = q0 + ty * 4 + i;
        float inv = 1.f / l_i[i];
        *(float4*)(yb + (size_t)r * CDIM + tx * 4) =
            make_float4(o[i][0] * inv, o[i][1] * inv, o[i][2] * inv, o[i][3] * inv);
    }
}

// ---------------------------------------------------------------------------
extern "C" void kernel_launch(void* const* d_in, const int* in_sizes, int n_in,
                              void* d_out, int out_size)
{
    const float* x      = (const float*)d_in[0];   // (B,T,C)
    const float* w_attn = (const float*)d_in[1];   // (3C,C)
    const float* w_proj = (const float*)d_in[2];   // (C,C)
    float* out = (float*)d_out;                    // (B,T,C)

    float* qkv = nullptr;
    float* yb  = nullptr;
    cudaGetSymbolAddress((void**)&qkv, g_qkv);
    cudaGetSymbolAddress((void**)&yb, g_y);

    const int M = BATCH * TFULL;          // 8192

    // 1) qkv = x @ w_attn^T   : (8192 x 3072)
    gemm_nt_tc<<<dim3(3 * CDIM / 128, M / 128), 256>>>(x, w_attn, qkv, M, 3 * CDIM, CDIM);

    // 2) y = causal_attention(qkv)
    flash_attn<<<dim3(TFULL / 64, BATCH * NHEAD), 256>>>(qkv, yb);

    // 3) out = y @ w_proj^T   : (8192 x 1024)
    gemm_nt_tc<<<dim3(CDIM / 128, M / 128), 256>>>(yb, w_proj, out, M, CDIM, CDIM);
}

// round 11
// speedup vs baseline: 1.3452x; 1.0865x over previous
#include <cuda_runtime.h>
#include <cstdint>

#define BATCH 4
#define TFULL 2048
#define CDIM  1024
#define NHEAD 16
#define HDIM  64

// Scratch (allocation-free rule: __device__ globals)
__device__ float g_qkv[(size_t)BATCH * TFULL * 3 * CDIM];  // (B,T,3C) ~100.7 MB
__device__ float g_y[(size_t)BATCH * TFULL * CDIM];        // (B,T,C)  ~33.5 MB

__device__ __forceinline__ uint32_t f2tf32(float f) {
    uint32_t u;
    asm("cvt.rna.tf32.f32 %0, %1;" : "=r"(u) : "f"(f));
    return u;
}

// 4-way register select (compiles to SELP chain, no local-mem indexing)
__device__ __forceinline__ float pick4(const float v[4], int j) {
    float r = v[0];
    r = (j == 1) ? v[1] : r;
    r = (j == 2) ? v[2] : r;
    r = (j == 3) ? v[3] : r;
    return r;
}

#define MMA_TF32(d, a, b)                                                      \
    asm volatile(                                                              \
        "mma.sync.aligned.m16n8k8.row.col.f32.tf32.tf32.f32 "                  \
        "{%0,%1,%2,%3}, {%4,%5,%6,%7}, {%8,%9}, {%0,%1,%2,%3};"                \
        : "+f"(d[0]), "+f"(d[1]), "+f"(d[2]), "+f"(d[3])                       \
        : "r"(a.x), "r"(a.y), "r"(a.z), "r"(a.w), "r"(b.x), "r"(b.y))

// ---------------------------------------------------------------------------
// NT GEMM on tf32 tensor cores, double-buffered, bank-conflict-fixed stores.
// C[m,n] = sum_k A[m,k]*B[n,k]. 128x128 tile, k-chunk 16, 8 warps 64x32 each.
// Fragment-store uses per-lane component rotation so each STS instruction's
// 32 lanes hit >=16 distinct banks (A: 2-way floor, B: conflict-free) instead
// of the previous 8-way conflict. Addresses/values unchanged -> same numerics.
// ---------------------------------------------------------------------------
__global__ void __launch_bounds__(256, 2) gemm_nt_tc(const float* __restrict__ A,
                                                     const float* __restrict__ B,
                                                     float* __restrict__ C,
                                                     int M, int N, int K)
{
    __shared__ uint32_t AF[2][8 * 2 * 32 * 4];   // 2 x 8 KB
    __shared__ uint32_t BF[2][16 * 2 * 32 * 2];  // 2 x 8 KB

    const int tid  = threadIdx.x;
    const int lane = tid & 31;
    const int warp = tid >> 5;
    const int wy = warp >> 2;
    const int wx = warp & 3;
    const int bm = blockIdx.y * 128;
    const int bn = blockIdx.x * 128;

    float acc[4][4][4];
#pragma unroll
    for (int i = 0; i < 4; ++i)
#pragma unroll
        for (int j = 0; j < 4; ++j)
#pragma unroll
            for (int r = 0; r < 4; ++r) acc[i][j][r] = 0.f;

    const int lrow0 = tid >> 2;          // 0..63
    const int lkk   = (tid & 3) * 4;     // 0,4,8,12
    const int m7    = lrow0 & 7;         // same for both row groups (+64)
    const int cgrp  = lkk >> 2;          // 0..3
    const int rotA  = (m7 >> 1) & 3;
    const int rotB  = ((m7 >> 2) + 2 * (cgrp >> 1)) & 3;

    // Precomputed fragment-store bases (validated layout from round 4)
    int abase[2], bbase[2];
#pragma unroll
    for (int l = 0; l < 2; ++l) {
        int row = lrow0 + l * 64;
        {
            int mt = row >> 4, r = row & 15;
            int ks = lkk >> 3;
            int chalf = (lkk & 7) >> 2;
            int reg = (r >> 3) + (chalf << 1);
            abase[l] = ((mt * 2 + ks) * 32 + (r & 7) * 4) * 4 + reg;
        }
        {
            int nt = row >> 3, n = row & 7;
            int ks = lkk >> 3;
            int reg = (lkk & 7) >> 2;
            bbase[l] = ((nt * 2 + ks) * 32 + n * 4) * 2 + reg;
        }
    }

    float4 pa[2], pb[2];

    auto load_chunk = [&](int k0) {
#pragma unroll
        for (int l = 0; l < 2; ++l) {
            int row = lrow0 + l * 64;
            pa[l] = *(const float4*)(A + (size_t)(bm + row) * K + k0 + lkk);
            pb[l] = *(const float4*)(B + (size_t)(bn + row) * K + k0 + lkk);
        }
    };
    // Per-lane rotated store order: component j stored in round rho where
    // j = (rho + rot) & 3. Same address/value pairs as the naive loop; only
    // the per-instruction lane->bank pattern changes (8-way -> <=2-way).
    auto store_chunk = [&](int buf) {
#pragma unroll
        for (int l = 0; l < 2; ++l) {
            const float va[4] = {pa[l].x, pa[l].y, pa[l].z, pa[l].w};
            const float vb[4] = {pb[l].x, pb[l].y, pb[l].z, pb[l].w};
#pragma unroll
            for (int rho = 0; rho < 4; ++rho) {
                int ja = (rho + rotA) & 3;
                AF[buf][abase[l] + ja * 4] = f2tf32(pick4(va, ja));
                int jb = (rho + rotB) & 3;
                BF[buf][bbase[l] + jb * 2] = f2tf32(pick4(vb, jb));
            }
        }
    };

    const int NCH = K >> 4;   // chunks of 16

    // Prologue: chunk 0 -> buf 0; chunk 1 -> regs
    load_chunk(0);
    store_chunk(0);
    __syncthreads();
    load_chunk(16);

    for (int i = 0; i < NCH; ++i) {
        const int cur = i & 1;
        if (i + 1 < NCH) store_chunk(1 - cur);      // regs hold chunk i+1
        if (i + 2 < NCH) load_chunk((i + 2) << 4);  // refill regs (after store)

#pragma unroll
        for (int ks = 0; ks < 2; ++ks) {
            uint4 a[4]; uint2 b[4];
#pragma unroll
            for (int mt = 0; mt < 4; ++mt) {
                int mtg = wy * 4 + mt;
                a[mt] = *(const uint4*)&AF[cur][((mtg * 2 + ks) * 32 + lane) * 4];
            }
#pragma unroll
            for (int nt = 0; nt < 4; ++nt) {
                int ntg = wx * 4 + nt;
                b[nt] = *(const uint2*)&BF[cur][((ntg * 2 + ks) * 32 + lane) * 2];
            }
#pragma unroll
            for (int mt = 0; mt < 4; ++mt)
#pragma unroll
                for (int nt = 0; nt < 4; ++nt)
                    MMA_TF32(acc[mt][nt], a[mt], b[nt]);
        }
        __syncthreads();   // compute(i) done; stores of i+1 visible
    }

#pragma unroll
    for (int mt = 0; mt < 4; ++mt) {
        int row0 = bm + wy * 64 + mt * 16 + (lane >> 2);
#pragma unroll
        for (int nt = 0; nt < 4; ++nt) {
            int col = bn + wx * 32 + nt * 8 + 2 * (lane & 3);
            *(float2*)(C + (size_t)row0 * N + col) =
                make_float2(acc[mt][nt][0], acc[mt][nt][1]);
            *(float2*)(C + (size_t)(row0 + 8) * N + col) =
                make_float2(acc[mt][nt][2], acc[mt][nt][3]);
        }
    }
}

// ---------------------------------------------------------------------------
// Causal flash attention, fp32 SIMT (validated round-3/4 version, ~1150us).
// ---------------------------------------------------------------------------
__global__ void __launch_bounds__(256) flash_attn(const float* __restrict__ qkv,
                                                  float* __restrict__ y)
{
    __shared__ float Qt[64 * 64];   // Q^T, swizzled: Qt[d*64 + (r ^ (d&60))]
    __shared__ float KPt[64 * 64];  // K^T (swizzled), then P^T (swizzled)
    __shared__ float Vs[64 * 64];   // V row-major

    const int qt = (gridDim.x - 1) - blockIdx.x;
    const int bh = blockIdx.y;
    const int b = bh >> 4;
    const int h = bh & 15;
    const int q0 = qt * 64;
    const int tid = threadIdx.x;
    const int tx = tid & 15;
    const int ty = tid >> 4;
    const size_t rs = 3 * CDIM;

    const float* qb = qkv + (size_t)b * TFULL * rs + (size_t)h * HDIM;
    const float* kb = qb + CDIM;
    const float* vb = qb + 2 * CDIM;

#pragma unroll
    for (int l = 0; l < 4; ++l) {
        int i = tid + l * 256;
        int r = i >> 4;
        int d4 = (i & 15) * 4;
        float4 q = *(const float4*)(qb + (size_t)(q0 + r) * rs + d4);
        Qt[(d4 + 0) * 64 + (r ^ ((d4 + 0) & 60))] = q.x * 0.125f;
        Qt[(d4 + 1) * 64 + (r ^ ((d4 + 1) & 60))] = q.y * 0.125f;
        Qt[(d4 + 2) * 64 + (r ^ ((d4 + 2) & 60))] = q.z * 0.125f;
        Qt[(d4 + 3) * 64 + (r ^ ((d4 + 3) & 60))] = q.w * 0.125f;
    }

    float m_i[4], l_i[4], o[4][4];
#pragma unroll
    for (int i = 0; i < 4; ++i) {
        m_i[i] = -1e30f;
        l_i[i] = 0.f;
#pragma unroll
        for (int j = 0; j < 4; ++j) o[i][j] = 0.f;
    }

    for (int kt = 0; kt <= qt; ++kt) {
        const int k0 = kt * 64;
        __syncthreads();

#pragma unroll
        for (int l = 0; l < 4; ++l) {
            int i = tid + l * 256;
            int r = i >> 4;
            int d4 = (i & 15) * 4;
            float4 kx = *(const float4*)(kb + (size_t)(k0 + r) * rs + d4);
            KPt[(d4 + 0) * 64 + (r ^ ((d4 + 0) & 60))] = kx.x;
            KPt[(d4 + 1) * 64 + (r ^ ((d4 + 1) & 60))] = kx.y;
            KPt[(d4 + 2) * 64 + (r ^ ((d4 + 2) & 60))] = kx.z;
            KPt[(d4 + 3) * 64 + (r ^ ((d4 + 3) & 60))] = kx.w;
            float4 vx = *(const float4*)(vb + (size_t)(k0 + r) * rs + d4);
            *(float4*)&Vs[r * 64 + d4] = vx;
        }
        __syncthreads();

        float s[4][4];
#pragma unroll
        for (int i = 0; i < 4; ++i)
#pragma unroll
            for (int j = 0; j < 4; ++j) s[i][j] = 0.f;

#pragma unroll 16
        for (int d = 0; d < 64; ++d) {
            float4 qv = *(const float4*)&Qt[d * 64 + ((ty * 4) ^ (d & 60))];
            float4 kv = *(const float4*)&KPt[d * 64 + ((tx * 4) ^ (d & 60))];
            s[0][0] += qv.x * kv.x; s[0][1] += qv.x * kv.y; s[0][2] += qv.x * kv.z; s[0][3] += qv.x * kv.w;
            s[1][0] += qv.y * kv.x; s[1][1] += qv.y * kv.y; s[1][2] += qv.y * kv.z; s[1][3] += qv.y * kv.w;
            s[2][0] += qv.z * kv.x; s[2][1] += qv.z * kv.y; s[2][2] += qv.z * kv.z; s[2][3] += qv.z * kv.w;
            s[3][0] += qv.w * kv.x; s[3][1] += qv.w * kv.y; s[3][2] += qv.w * kv.z; s[3][3] += qv.w * kv.w;
        }

        if (kt == qt) {
#pragma unroll
            for (int i = 0; i < 4; ++i)
#pragma unroll
                for (int j = 0; j < 4; ++j)
                    if (tx * 4 + j > ty * 4 + i) s[i][j] = -1e30f;
        }

        float mt[4], ls[4];
#pragma unroll
        for (int i = 0; i < 4; ++i)
            mt[i] = fmaxf(fmaxf(s[i][0], s[i][1]), fmaxf(s[i][2], s[i][3]));
#pragma unroll
        for (int off = 1; off < 16; off <<= 1)
#pragma unroll
            for (int i = 0; i < 4; ++i)
                mt[i] = fmaxf(mt[i], __shfl_xor_sync(0xffffffffu, mt[i], off));

#pragma unroll
        for (int i = 0; i < 4; ++i) {
            float mn = fmaxf(m_i[i], mt[i]);
            float sc = __expf(m_i[i] - mn);
            m_i[i] = mn;
            l_i[i] *= sc;
#pragma unroll
            for (int j = 0; j < 4; ++j) o[i][j] *= sc;
            float lsum = 0.f;
#pragma unroll
            for (int j = 0; j < 4; ++j) {
                float p = __expf(s[i][j] - mn);
                s[i][j] = p;
                lsum += p;
            }
            ls[i] = lsum;
        }
#pragma unroll
        for (int off = 1; off < 16; off <<= 1)
#pragma unroll
            for (int i = 0; i < 4; ++i)
                ls[i] += __shfl_xor_sync(0xffffffffu, ls[i], off);
#pragma unroll
        for (int i = 0; i < 4; ++i) l_i[i] += ls[i];

        __syncthreads();
#pragma unroll
        for (int j = 0; j < 4; ++j) {
            int n = tx * 4 + j;
#pragma unroll
            for (int i = 0; i < 4; ++i)
                KPt[n * 64 + ((ty * 4 + i) ^ (n & 60))] = s[i][j];
        }
        __syncthreads();

#pragma unroll 16
        for (int k = 0; k < 64; ++k) {
            float4 pv = *(const float4*)&KPt[k * 64 + ((ty * 4) ^ (k & 60))];
            float4 vv = *(const float4*)&Vs[k * 64 + tx * 4];
            o[0][0] += pv.x * vv.x; o[0][1] += pv.x * vv.y; o[0][2] += pv.x * vv.z; o[0][3] += pv.x * vv.w;
            o[1][0] += pv.y * vv.x; o[1][1] += pv.y * vv.y; o[1][2] += pv.y * vv.z; o[1][3] += pv.y * vv.w;
            o[2][0] += pv.z * vv.x; o[2][1] += pv.z * vv.y; o[2][2] += pv.z * vv.z; o[2][3] += pv.z * vv.w;
            o[3][0] += pv.w * vv.x; o[3][1] += pv.w * vv.y; o[3][2] += pv.w * vv.z; o[3][3] += pv.w * vv.w;
        }
    }

    float* yb = y + (size_t)b * TFULL * CDIM + (size_t)h * HDIM;
#pragma unroll
    for (int i = 0; i < 4; ++i) {
        int r = q0 + ty * 4 + i;
        float inv = 1.f / l_i[i];
        *(float4*)(yb + (size_t)r * CDIM + tx * 4) =
            make_float4(o[i][0] * inv, o[i][1] * inv, o[i][2] * inv, o[i][3] * inv);
    }
}

// ---------------------------------------------------------------------------
extern "C" void kernel_launch(void* const* d_in, const int* in_sizes, int n_in,
                              void* d_out, int out_size)
{
    const float* x      = (const float*)d_in[0];   // (B,T,C)
    const float* w_attn = (const float*)d_in[1];   // (3C,C)
    const float* w_proj = (const float*)d_in[2];   // (C,C)
    float* out = (float*)d_out;                    // (B,T,C)

    float* qkv = nullptr;
    float* yb  = nullptr;
    cudaGetSymbolAddress((void**)&qkv, g_qkv);
    cudaGetSymbolAddress((void**)&yb, g_y);

    const int M = BATCH * TFULL;          // 8192

    // 1) qkv = x @ w_attn^T   : (8192 x 3072)
    gemm_nt_tc<<<dim3(3 * CDIM / 128, M / 128), 256>>>(x, w_attn, qkv, M, 3 * CDIM, CDIM);

    // 2) y = causal_attention(qkv)
    flash_attn<<<dim3(TFULL / 64, BATCH * NHEAD), 256>>>(qkv, yb);

    // 3) out = y @ w_proj^T   : (8192 x 1024)
    gemm_nt_tc<<<dim3(CDIM / 128, M / 128), 256>>>(yb, w_proj, out, M, CDIM, CDIM);
}

// round 12
// speedup vs baseline: 1.5202x; 1.1301x over previous
#include <cuda_runtime.h>
#include <cstdint>

#define BATCH 4
#define TFULL 2048
#define CDIM  1024
#define NHEAD 16
#define HDIM  64

// Scratch (allocation-free rule: __device__ globals)
__device__ float g_qkv[(size_t)BATCH * TFULL * 3 * CDIM];  // (B,T,3C) ~100.7 MB
__device__ float g_y[(size_t)BATCH * TFULL * CDIM];        // (B,T,C)  ~33.5 MB

__device__ __forceinline__ uint32_t f2tf32(float f) {
    uint32_t u;
    asm("cvt.rna.tf32.f32 %0, %1;" : "=r"(u) : "f"(f));
    return u;
}

// 4-way register select (compiles to SELP chain, no local-mem indexing)
__device__ __forceinline__ float pick4(const float v[4], int j) {
    float r = v[0];
    r = (j == 1) ? v[1] : r;
    r = (j == 2) ? v[2] : r;
    r = (j == 3) ? v[3] : r;
    return r;
}

#define MMA_TF32(d, a, b)                                                      \
    asm volatile(                                                              \
        "mma.sync.aligned.m16n8k8.row.col.f32.tf32.tf32.f32 "                  \
        "{%0,%1,%2,%3}, {%4,%5,%6,%7}, {%8,%9}, {%0,%1,%2,%3};"                \
        : "+f"(d[0]), "+f"(d[1]), "+f"(d[2]), "+f"(d[3])                       \
        : "r"(a.x), "r"(a.y), "r"(a.z), "r"(a.w), "r"(b.x), "r"(b.y))

// ---------------------------------------------------------------------------
// NT GEMM on tf32 tensor cores (unchanged from round 11, validated 480us).
// ---------------------------------------------------------------------------
__global__ void __launch_bounds__(256, 2) gemm_nt_tc(const float* __restrict__ A,
                                                     const float* __restrict__ B,
                                                     float* __restrict__ C,
                                                     int M, int N, int K)
{
    __shared__ uint32_t AF[2][8 * 2 * 32 * 4];
    __shared__ uint32_t BF[2][16 * 2 * 32 * 2];

    const int tid  = threadIdx.x;
    const int lane = tid & 31;
    const int warp = tid >> 5;
    const int wy = warp >> 2;
    const int wx = warp & 3;
    const int bm = blockIdx.y * 128;
    const int bn = blockIdx.x * 128;

    float acc[4][4][4];
#pragma unroll
    for (int i = 0; i < 4; ++i)
#pragma unroll
        for (int j = 0; j < 4; ++j)
#pragma unroll
            for (int r = 0; r < 4; ++r) acc[i][j][r] = 0.f;

    const int lrow0 = tid >> 2;
    const int lkk   = (tid & 3) * 4;
    const int m7    = lrow0 & 7;
    const int cgrp  = lkk >> 2;
    const int rotA  = (m7 >> 1) & 3;
    const int rotB  = ((m7 >> 2) + 2 * (cgrp >> 1)) & 3;

    int abase[2], bbase[2];
#pragma unroll
    for (int l = 0; l < 2; ++l) {
        int row = lrow0 + l * 64;
        {
            int mt = row >> 4, r = row & 15;
            int ks = lkk >> 3;
            int chalf = (lkk & 7) >> 2;
            int reg = (r >> 3) + (chalf << 1);
            abase[l] = ((mt * 2 + ks) * 32 + (r & 7) * 4) * 4 + reg;
        }
        {
            int nt = row >> 3, n = row & 7;
            int ks = lkk >> 3;
            int reg = (lkk & 7) >> 2;
            bbase[l] = ((nt * 2 + ks) * 32 + n * 4) * 2 + reg;
        }
    }

    float4 pa[2], pb[2];

    auto load_chunk = [&](int k0) {
#pragma unroll
        for (int l = 0; l < 2; ++l) {
            int row = lrow0 + l * 64;
            pa[l] = *(const float4*)(A + (size_t)(bm + row) * K + k0 + lkk);
            pb[l] = *(const float4*)(B + (size_t)(bn + row) * K + k0 + lkk);
        }
    };
    auto store_chunk = [&](int buf) {
#pragma unroll
        for (int l = 0; l < 2; ++l) {
            const float va[4] = {pa[l].x, pa[l].y, pa[l].z, pa[l].w};
            const float vb[4] = {pb[l].x, pb[l].y, pb[l].z, pb[l].w};
#pragma unroll
            for (int rho = 0; rho < 4; ++rho) {
                int ja = (rho + rotA) & 3;
                AF[buf][abase[l] + ja * 4] = f2tf32(pick4(va, ja));
                int jb = (rho + rotB) & 3;
                BF[buf][bbase[l] + jb * 2] = f2tf32(pick4(vb, jb));
            }
        }
    };

    const int NCH = K >> 4;

    load_chunk(0);
    store_chunk(0);
    __syncthreads();
    load_chunk(16);

    for (int i = 0; i < NCH; ++i) {
        const int cur = i & 1;
        if (i + 1 < NCH) store_chunk(1 - cur);
        if (i + 2 < NCH) load_chunk((i + 2) << 4);

#pragma unroll
        for (int ks = 0; ks < 2; ++ks) {
            uint4 a[4]; uint2 b[4];
#pragma unroll
            for (int mt = 0; mt < 4; ++mt) {
                int mtg = wy * 4 + mt;
                a[mt] = *(const uint4*)&AF[cur][((mtg * 2 + ks) * 32 + lane) * 4];
            }
#pragma unroll
            for (int nt = 0; nt < 4; ++nt) {
                int ntg = wx * 4 + nt;
                b[nt] = *(const uint2*)&BF[cur][((ntg * 2 + ks) * 32 + lane) * 2];
            }
#pragma unroll
            for (int mt = 0; mt < 4; ++mt)
#pragma unroll
                for (int nt = 0; nt < 4; ++nt)
                    MMA_TF32(acc[mt][nt], a[mt], b[nt]);
        }
        __syncthreads();
    }

#pragma unroll
    for (int mt = 0; mt < 4; ++mt) {
        int row0 = bm + wy * 64 + mt * 16 + (lane >> 2);
#pragma unroll
        for (int nt = 0; nt < 4; ++nt) {
            int col = bn + wx * 32 + nt * 8 + 2 * (lane & 3);
            *(float2*)(C + (size_t)row0 * N + col) =
                make_float2(acc[mt][nt][0], acc[mt][nt][1]);
            *(float2*)(C + (size_t)(row0 + 8) * N + col) =
                make_float2(acc[mt][nt][2], acc[mt][nt][3]);
        }
    }
}

// ---------------------------------------------------------------------------
// Causal flash attention v2 on tf32 tensor cores.
// q-tile 128, kv-tile 64. 8 warps: wm=warp&3 (32 rows = 2 m16 tiles),
// wn=warp>>2 (32-col half = 4 n8 tiles).
// Q,K: hi+residual (3-mma QK^T, fp32-exact). P,V: single tf32 (1-mma PV).
// All fragment stores use rotation/skew for low bank conflict.
// Smem (u32): QH 0..8192, QR ..16384, K hi 16384..20480, K res ..24576
//   (P overwrites K region, 8192 u32), V^T 24576..28800 (skewed),
//   smax 28800..29056, ssum 29056..29312.
// ---------------------------------------------------------------------------
__global__ void __launch_bounds__(256) flash_attn_tc2(const float* __restrict__ qkv,
                                                      float* __restrict__ y)
{
    extern __shared__ uint32_t dsm[];
    uint32_t* QH = dsm;
    uint32_t* QR = dsm + 8192;
    uint32_t* KP = dsm + 16384;   // K hi, then P (A-layout, 8192 u32 total)
    uint32_t* KR = dsm + 20480;   // K res
    uint32_t* VT = dsm + 24576;   // V^T single, +skew
    float* smax = (float*)(dsm + 28800);   // [2][128]
    float* ssum = (float*)(dsm + 29056);   // [2][128]

    const int qt = (gridDim.x - 1) - blockIdx.x;
    const int bh = blockIdx.y;
    const int b = bh >> 4, h = bh & 15;
    const int q0 = qt * 128;
    const int tid = threadIdx.x, lane = tid & 31, warp = tid >> 5;
    const int wm = warp & 3, wn = warp >> 2;
    const size_t rs = 3 * CDIM;

    const float* qb = qkv + (size_t)b * TFULL * rs + (size_t)h * HDIM;
    const float* kb = qb + CDIM;
    const float* vb = qb + 2 * CDIM;

    // ---- build Q fragments (A-layout), hi+res, scale folded ----
#pragma unroll
    for (int l = 0; l < 8; ++l) {
        int i = tid + l * 256;
        int r = i >> 4;              // 0..127
        int d4 = (i & 15) * 4;       // 0..60
        float4 q = *(const float4*)(qb + (size_t)(q0 + r) * rs + d4);
        float v[4] = {q.x * 0.125f, q.y * 0.125f, q.z * 0.125f, q.w * 0.125f};
        int mt = r >> 4, m = r & 15, ks = d4 >> 3, ch = (d4 & 7) >> 2;
        int base = ((mt * 8 + ks) * 32 + (m & 7) * 4) * 4 + (m >> 3) + 2 * ch;
        int rot = ((r & 7) >> 1) & 3;
#pragma unroll
        for (int rho = 0; rho < 4; ++rho) {
            int j = (rho + rot) & 3;
            float val = pick4(v, j);
            uint32_t hi = f2tf32(val);
            QH[base + j * 4] = hi;
            QR[base + j * 4] = f2tf32(val - __uint_as_float(hi));
        }
    }

    float m_i[2][2], l_i[2][2], o[2][4][4];
#pragma unroll
    for (int mt = 0; mt < 2; ++mt) {
        m_i[mt][0] = -1e30f; m_i[mt][1] = -1e30f;
        l_i[mt][0] = 0.f;    l_i[mt][1] = 0.f;
#pragma unroll
        for (int nt = 0; nt < 4; ++nt)
#pragma unroll
            for (int rg = 0; rg < 4; ++rg) o[mt][nt][rg] = 0.f;
    }

    const int ktmax = 2 * qt + 1;
    for (int kt = 0; kt <= ktmax; ++kt) {
        const int k0 = kt * 64;

        // prefetch K/V into registers (overlaps the barrier wait)
        float4 kx[4], vx[4];
#pragma unroll
        for (int l = 0; l < 4; ++l) {
            int i = tid + l * 256;
            int r = i >> 4, d4 = (i & 15) * 4;
            kx[l] = *(const float4*)(kb + (size_t)(k0 + r) * rs + d4);
            vx[l] = *(const float4*)(vb + (size_t)(k0 + r) * rs + d4);
        }
        __syncthreads();   // prev-tile PV reads done; Q visible on first iter

        // ---- store K (hi+res, B-layout) and V^T (single, B-layout+skew) ----
#pragma unroll
        for (int l = 0; l < 4; ++l) {
            int i = tid + l * 256;
            int r = i >> 4, d4 = (i & 15) * 4;
            float kv[4] = {kx[l].x, kx[l].y, kx[l].z, kx[l].w};
            float vv[4] = {vx[l].x, vx[l].y, vx[l].z, vx[l].w};
            int nt = r >> 3, n = r & 7, ks = d4 >> 3, ch = (d4 & 7) >> 2;
            int kbase = ((nt * 8 + ks) * 32 + n * 4) * 2 + ch;
            int rotK = ((n >> 2) + 2 * ((d4 >> 3) & 1)) & 3;
            int ntv = d4 >> 3, ksv = r >> 3, kk = r & 7;
            int vbase = ((ntv * 8 + ksv) * 32 + (d4 & 7) * 4 + (kk & 3)) * 2
                      + (kk >> 2) + ntv * 2;
            int rotV = (d4 >> 2) & 3;
#pragma unroll
            for (int rho = 0; rho < 4; ++rho) {
                int jk = (rho + rotK) & 3;
                float valk = pick4(kv, jk);
                uint32_t hi = f2tf32(valk);
                KP[kbase + jk * 2] = hi;
                KR[kbase + jk * 2] = f2tf32(valk - __uint_as_float(hi));
                int jv = (rho + rotV) & 3;
                VT[vbase + jv * 8] = f2tf32(pick4(vv, jv));
            }
        }
        __syncthreads();

        // ---- S = Q K^T (3-mma split) ----
        float s[2][4][4];
#pragma unroll
        for (int mt = 0; mt < 2; ++mt)
#pragma unroll
            for (int nt = 0; nt < 4; ++nt)
#pragma unroll
                for (int rg = 0; rg < 4; ++rg) s[mt][nt][rg] = 0.f;

#pragma unroll
        for (int ks = 0; ks < 8; ++ks) {
            uint4 aH[2], aR[2];
#pragma unroll
            for (int mt = 0; mt < 2; ++mt) {
                int mtg = wm * 2 + mt;
                aH[mt] = ((const uint4*)QH)[(mtg * 8 + ks) * 32 + lane];
                aR[mt] = ((const uint4*)QR)[(mtg * 8 + ks) * 32 + lane];
            }
#pragma unroll
            for (int nt = 0; nt < 4; ++nt) {
                int ntg = wn * 4 + nt;
                uint2 bH = ((const uint2*)KP)[(ntg * 8 + ks) * 32 + lane];
                uint2 bR = ((const uint2*)KR)[(ntg * 8 + ks) * 32 + lane];
#pragma unroll
                for (int mt = 0; mt < 2; ++mt) {
                    MMA_TF32(s[mt][nt], aH[mt], bH);
                    MMA_TF32(s[mt][nt], aH[mt], bR);
                    MMA_TF32(s[mt][nt], aR[mt], bH);
                }
            }
        }

        // ---- causal mask (only last two k-tiles can cross the diagonal) ----
        if (kt >= 2 * qt) {
#pragma unroll
            for (int mt = 0; mt < 2; ++mt)
#pragma unroll
                for (int nt = 0; nt < 4; ++nt)
#pragma unroll
                    for (int rg = 0; rg < 4; ++rg) {
                        int gr = q0 + (wm * 2 + mt) * 16 + (lane >> 2) + 8 * (rg >> 1);
                        int gc = k0 + wn * 32 + nt * 8 + 2 * (lane & 3) + (rg & 1);
                        if (gc > gr) s[mt][nt][rg] = -1e30f;
                    }
        }

        // ---- row max: local -> quad shfl -> cross-warp-pair via smem ----
        float pm[2][2];
#pragma unroll
        for (int mt = 0; mt < 2; ++mt) {
            pm[mt][0] = -1e30f; pm[mt][1] = -1e30f;
#pragma unroll
            for (int nt = 0; nt < 4; ++nt) {
                pm[mt][0] = fmaxf(pm[mt][0], fmaxf(s[mt][nt][0], s[mt][nt][1]));
                pm[mt][1] = fmaxf(pm[mt][1], fmaxf(s[mt][nt][2], s[mt][nt][3]));
            }
#pragma unroll
            for (int off = 1; off < 4; off <<= 1) {
                pm[mt][0] = fmaxf(pm[mt][0], __shfl_xor_sync(0xffffffffu, pm[mt][0], off));
                pm[mt][1] = fmaxf(pm[mt][1], __shfl_xor_sync(0xffffffffu, pm[mt][1], off));
            }
        }
        if ((lane & 3) == 0) {
#pragma unroll
            for (int mt = 0; mt < 2; ++mt)
#pragma unroll
                for (int rh = 0; rh < 2; ++rh)
                    smax[wn * 128 + wm * 32 + mt * 16 + rh * 8 + (lane >> 2)] = pm[mt][rh];
        }
        __syncthreads();   // smax visible; all warps done reading K fragments

        float mn[2][2], sc[2][2];
#pragma unroll
        for (int mt = 0; mt < 2; ++mt)
#pragma unroll
            for (int rh = 0; rh < 2; ++rh) {
                int row = wm * 32 + mt * 16 + rh * 8 + (lane >> 2);
                float mtile = fmaxf(smax[row], smax[128 + row]);
                mn[mt][rh] = fmaxf(m_i[mt][rh], mtile);
                sc[mt][rh] = __expf(m_i[mt][rh] - mn[mt][rh]);
                m_i[mt][rh] = mn[mt][rh];
                l_i[mt][rh] *= sc[mt][rh];
            }
#pragma unroll
        for (int mt = 0; mt < 2; ++mt)
#pragma unroll
            for (int nt = 0; nt < 4; ++nt) {
                o[mt][nt][0] *= sc[mt][0]; o[mt][nt][1] *= sc[mt][0];
                o[mt][nt][2] *= sc[mt][1]; o[mt][nt][3] *= sc[mt][1];
            }

        // ---- p = exp(s - m); store P single tf32 (A-layout into KP) ----
        float ps[2][2] = {{0.f, 0.f}, {0.f, 0.f}};
        const int rotP = lane & 3;
#pragma unroll
        for (int mt = 0; mt < 2; ++mt) {
            int mtg = wm * 2 + mt;
#pragma unroll
            for (int nt = 0; nt < 4; ++nt) {
                float p4[4];
#pragma unroll
                for (int rg = 0; rg < 4; ++rg) {
                    p4[rg] = __expf(s[mt][nt][rg] - mn[mt][rg >> 1]);
                    ps[mt][rg >> 1] += p4[rg];
                }
                int ksp = wn * 4 + nt;
#pragma unroll
                for (int rho = 0; rho < 4; ++rho) {
                    int rg = (rho + rotP) & 3;
                    int idx = ((mtg * 8 + ksp) * 32 + (lane >> 2) * 4
                               + 2 * (lane & 1) + (rg & 1)) * 4
                            + (rg >> 1) + 2 * ((lane >> 1) & 1);
                    KP[idx] = f2tf32(pick4(p4, rg));
                }
            }
        }
#pragma unroll
        for (int mt = 0; mt < 2; ++mt)
#pragma unroll
            for (int off = 1; off < 4; off <<= 1) {
                ps[mt][0] += __shfl_xor_sync(0xffffffffu, ps[mt][0], off);
                ps[mt][1] += __shfl_xor_sync(0xffffffffu, ps[mt][1], off);
            }
        if ((lane & 3) == 0) {
#pragma unroll
            for (int mt = 0; mt < 2; ++mt)
#pragma unroll
                for (int rh = 0; rh < 2; ++rh)
                    ssum[wn * 128 + wm * 32 + mt * 16 + rh * 8 + (lane >> 2)] = ps[mt][rh];
        }
        __syncthreads();   // P + ssum visible

#pragma unroll
        for (int mt = 0; mt < 2; ++mt)
#pragma unroll
            for (int rh = 0; rh < 2; ++rh) {
                int row = wm * 32 + mt * 16 + rh * 8 + (lane >> 2);
                l_i[mt][rh] += ssum[row] + ssum[128 + row];
            }

        // ---- O += P V (single mma) ----
#pragma unroll
        for (int ks = 0; ks < 8; ++ks) {
            uint4 aP[2];
#pragma unroll
            for (int mt = 0; mt < 2; ++mt)
                aP[mt] = ((const uint4*)KP)[((wm * 2 + mt) * 8 + ks) * 32 + lane];
#pragma unroll
            for (int nt = 0; nt < 4; ++nt) {
                int ntg = wn * 4 + nt;
                uint2 bV = ((const uint2*)VT)[(ntg * 8 + ks) * 32 + lane + ntg];
#pragma unroll
                for (int mt = 0; mt < 2; ++mt)
                    MMA_TF32(o[mt][nt], aP[mt], bV);
            }
        }
    }

    // ---- epilogue: O / l ----
    float* yb = y + (size_t)b * TFULL * CDIM + (size_t)h * HDIM;
#pragma unroll
    for (int mt = 0; mt < 2; ++mt) {
        float inv0 = 1.f / l_i[mt][0];
        float inv1 = 1.f / l_i[mt][1];
        int gr0 = q0 + (wm * 2 + mt) * 16 + (lane >> 2);
#pragma unroll
        for (int nt = 0; nt < 4; ++nt) {
            int col = wn * 32 + nt * 8 + 2 * (lane & 3);
            *(float2*)(yb + (size_t)gr0 * CDIM + col) =
                make_float2(o[mt][nt][0] * inv0, o[mt][nt][1] * inv0);
            *(float2*)(yb + (size_t)(gr0 + 8) * CDIM + col) =
                make_float2(o[mt][nt][2] * inv1, o[mt][nt][3] * inv1);
        }
    }
}

// ---------------------------------------------------------------------------
extern "C" void kernel_launch(void* const* d_in, const int* in_sizes, int n_in,
                              void* d_out, int out_size)
{
    const float* x      = (const float*)d_in[0];   // (B,T,C)
    const float* w_attn = (const float*)d_in[1];   // (3C,C)
    const float* w_proj = (const float*)d_in[2];   // (C,C)
    float* out = (float*)d_out;                    // (B,T,C)

    float* qkv = nullptr;
    float* yb  = nullptr;
    cudaGetSymbolAddress((void**)&qkv, g_qkv);
    cudaGetSymbolAddress((void**)&yb, g_y);

    const int M = BATCH * TFULL;              // 8192
    const int ATTN_SMEM = 29312 * 4;          // 117248 bytes

    cudaFuncSetAttribute(flash_attn_tc2,
                         cudaFuncAttributeMaxDynamicSharedMemorySize, ATTN_SMEM);

    // 1) qkv = x @ w_attn^T   : (8192 x 3072)
    gemm_nt_tc<<<dim3(3 * CDIM / 128, M / 128), 256>>>(x, w_attn, qkv, M, 3 * CDIM, CDIM);

    // 2) y = causal_attention(qkv), q-tile 128
    flash_attn_tc2<<<dim3(TFULL / 128, BATCH * NHEAD), 256, ATTN_SMEM>>>(qkv, yb);

    // 3) out = y @ w_proj^T   : (8192 x 1024)
    gemm_nt_tc<<<dim3(CDIM / 128, M / 128), 256>>>(yb, w_proj, out, M, CDIM, CDIM);
}

// round 14
// speedup vs baseline: 1.5291x; 1.0058x over previous
#include <cuda_runtime.h>
#include <cstdint>

#define BATCH 4
#define TFULL 2048
#define CDIM  1024
#define NHEAD 16
#define HDIM  64

// Scratch (allocation-free rule: __device__ globals)
__device__ float g_qkv[(size_t)BATCH * TFULL * 3 * CDIM];  // (B,T,3C) ~100.7 MB
__device__ float g_y[(size_t)BATCH * TFULL * CDIM];        // (B,T,C)  ~33.5 MB

__device__ __forceinline__ uint32_t f2tf32(float f) {
    uint32_t u;
    asm("cvt.rna.tf32.f32 %0, %1;" : "=r"(u) : "f"(f));
    return u;
}

// 4-way register select (compiles to SELP chain, no local-mem indexing)
__device__ __forceinline__ float pick4(const float v[4], int j) {
    float r = v[0];
    r = (j == 1) ? v[1] : r;
    r = (j == 2) ? v[2] : r;
    r = (j == 3) ? v[3] : r;
    return r;
}

#define MMA_TF32(d, a, b)                                                      \
    asm volatile(                                                              \
        "mma.sync.aligned.m16n8k8.row.col.f32.tf32.tf32.f32 "                  \
        "{%0,%1,%2,%3}, {%4,%5,%6,%7}, {%8,%9}, {%0,%1,%2,%3};"                \
        : "+f"(d[0]), "+f"(d[1]), "+f"(d[2]), "+f"(d[3])                       \
        : "r"(a.x), "r"(a.y), "r"(a.z), "r"(a.w), "r"(b.x), "r"(b.y))

// ---------------------------------------------------------------------------
// NT GEMM on tf32 tensor cores (unchanged from round 11, validated 480us).
// ---------------------------------------------------------------------------
__global__ void __launch_bounds__(256, 2) gemm_nt_tc(const float* __restrict__ A,
                                                     const float* __restrict__ B,
                                                     float* __restrict__ C,
                                                     int M, int N, int K)
{
    __shared__ uint32_t AF[2][8 * 2 * 32 * 4];
    __shared__ uint32_t BF[2][16 * 2 * 32 * 2];

    const int tid  = threadIdx.x;
    const int lane = tid & 31;
    const int warp = tid >> 5;
    const int wy = warp >> 2;
    const int wx = warp & 3;
    const int bm = blockIdx.y * 128;
    const int bn = blockIdx.x * 128;

    float acc[4][4][4];
#pragma unroll
    for (int i = 0; i < 4; ++i)
#pragma unroll
        for (int j = 0; j < 4; ++j)
#pragma unroll
            for (int r = 0; r < 4; ++r) acc[i][j][r] = 0.f;

    const int lrow0 = tid >> 2;
    const int lkk   = (tid & 3) * 4;
    const int m7    = lrow0 & 7;
    const int cgrp  = lkk >> 2;
    const int rotA  = (m7 >> 1) & 3;
    const int rotB  = ((m7 >> 2) + 2 * (cgrp >> 1)) & 3;

    int abase[2], bbase[2];
#pragma unroll
    for (int l = 0; l < 2; ++l) {
        int row = lrow0 + l * 64;
        {
            int mt = row >> 4, r = row & 15;
            int ks = lkk >> 3;
            int chalf = (lkk & 7) >> 2;
            int reg = (r >> 3) + (chalf << 1);
            abase[l] = ((mt * 2 + ks) * 32 + (r & 7) * 4) * 4 + reg;
        }
        {
            int nt = row >> 3, n = row & 7;
            int ks = lkk >> 3;
            int reg = (lkk & 7) >> 2;
            bbase[l] = ((nt * 2 + ks) * 32 + n * 4) * 2 + reg;
        }
    }

    float4 pa[2], pb[2];

    auto load_chunk = [&](int k0) {
#pragma unroll
        for (int l = 0; l < 2; ++l) {
            int row = lrow0 + l * 64;
            pa[l] = *(const float4*)(A + (size_t)(bm + row) * K + k0 + lkk);
            pb[l] = *(const float4*)(B + (size_t)(bn + row) * K + k0 + lkk);
        }
    };
    auto store_chunk = [&](int buf) {
#pragma unroll
        for (int l = 0; l < 2; ++l) {
            const float va[4] = {pa[l].x, pa[l].y, pa[l].z, pa[l].w};
            const float vb[4] = {pb[l].x, pb[l].y, pb[l].z, pb[l].w};
#pragma unroll
            for (int rho = 0; rho < 4; ++rho) {
                int ja = (rho + rotA) & 3;
                AF[buf][abase[l] + ja * 4] = f2tf32(pick4(va, ja));
                int jb = (rho + rotB) & 3;
                BF[buf][bbase[l] + jb * 2] = f2tf32(pick4(vb, jb));
            }
        }
    };

    const int NCH = K >> 4;

    load_chunk(0);
    store_chunk(0);
    __syncthreads();
    load_chunk(16);

    for (int i = 0; i < NCH; ++i) {
        const int cur = i & 1;
        if (i + 1 < NCH) store_chunk(1 - cur);
        if (i + 2 < NCH) load_chunk((i + 2) << 4);

#pragma unroll
        for (int ks = 0; ks < 2; ++ks) {
            uint4 a[4]; uint2 b[4];
#pragma unroll
            for (int mt = 0; mt < 4; ++mt) {
                int mtg = wy * 4 + mt;
                a[mt] = *(const uint4*)&AF[cur][((mtg * 2 + ks) * 32 + lane) * 4];
            }
#pragma unroll
            for (int nt = 0; nt < 4; ++nt) {
                int ntg = wx * 4 + nt;
                b[nt] = *(const uint2*)&BF[cur][((ntg * 2 + ks) * 32 + lane) * 2];
            }
#pragma unroll
            for (int mt = 0; mt < 4; ++mt)
#pragma unroll
                for (int nt = 0; nt < 4; ++nt)
                    MMA_TF32(acc[mt][nt], a[mt], b[nt]);
        }
        __syncthreads();
    }

#pragma unroll
    for (int mt = 0; mt < 4; ++mt) {
        int row0 = bm + wy * 64 + mt * 16 + (lane >> 2);
#pragma unroll
        for (int nt = 0; nt < 4; ++nt) {
            int col = bn + wx * 32 + nt * 8 + 2 * (lane & 3);
            *(float2*)(C + (size_t)row0 * N + col) =
                make_float2(acc[mt][nt][0], acc[mt][nt][1]);
            *(float2*)(C + (size_t)(row0 + 8) * N + col) =
                make_float2(acc[mt][nt][2], acc[mt][nt][3]);
        }
    }
}

// ---------------------------------------------------------------------------
// Causal flash attention v2 on tf32 tensor cores.
// q-tile 128, kv-tile 64. 8 warps: wm=warp&3 (32 rows = 2 m16 tiles),
// wn=warp>>2 (32-col half = 4 n8 tiles).
// Q,K: hi+residual (3-mma QK^T, fp32-exact). P,V: single tf32 (1-mma PV).
// All fragment stores use rotation/skew for low bank conflict.
// Smem (u32): QH 0..8192, QR ..16384, K hi 16384..20480, K res ..24576
//   (P overwrites K region, 8192 u32), V^T 24576..28800 (skewed),
//   smax 28800..29056, ssum 29056..29312.
// ---------------------------------------------------------------------------
__global__ void __launch_bounds__(256) flash_attn_tc2(const float* __restrict__ qkv,
                                                      float* __restrict__ y)
{
    extern __shared__ uint32_t dsm[];
    uint32_t* QH = dsm;
    uint32_t* QR = dsm + 8192;
    uint32_t* KP = dsm + 16384;   // K hi, then P (A-layout, 8192 u32 total)
    uint32_t* KR = dsm + 20480;   // K res
    uint32_t* VT = dsm + 24576;   // V^T single, +skew
    float* smax = (float*)(dsm + 28800);   // [2][128]
    float* ssum = (float*)(dsm + 29056);   // [2][128]

    const int qt = (gridDim.x - 1) - blockIdx.x;
    const int bh = blockIdx.y;
    const int b = bh >> 4, h = bh & 15;
    const int q0 = qt * 128;
    const int tid = threadIdx.x, lane = tid & 31, warp = tid >> 5;
    const int wm = warp & 3, wn = warp >> 2;
    const size_t rs = 3 * CDIM;

    const float* qb = qkv + (size_t)b * TFULL * rs + (size_t)h * HDIM;
    const float* kb = qb + CDIM;
    const float* vb = qb + 2 * CDIM;

    // ---- build Q fragments (A-layout), hi+res, scale folded ----
#pragma unroll
    for (int l = 0; l < 8; ++l) {
        int i = tid + l * 256;
        int r = i >> 4;              // 0..127
        int d4 = (i & 15) * 4;       // 0..60
        float4 q = *(const float4*)(qb + (size_t)(q0 + r) * rs + d4);
        float v[4] = {q.x * 0.125f, q.y * 0.125f, q.z * 0.125f, q.w * 0.125f};
        int mt = r >> 4, m = r & 15, ks = d4 >> 3, ch = (d4 & 7) >> 2;
        int base = ((mt * 8 + ks) * 32 + (m & 7) * 4) * 4 + (m >> 3) + 2 * ch;
        int rot = ((r & 7) >> 1) & 3;
#pragma unroll
        for (int rho = 0; rho < 4; ++rho) {
            int j = (rho + rot) & 3;
            float val = pick4(v, j);
            uint32_t hi = f2tf32(val);
            QH[base + j * 4] = hi;
            QR[base + j * 4] = f2tf32(val - __uint_as_float(hi));
        }
    }

    float m_i[2][2], l_i[2][2], o[2][4][4];
#pragma unroll
    for (int mt = 0; mt < 2; ++mt) {
        m_i[mt][0] = -1e30f; m_i[mt][1] = -1e30f;
        l_i[mt][0] = 0.f;    l_i[mt][1] = 0.f;
#pragma unroll
        for (int nt = 0; nt < 4; ++nt)
#pragma unroll
            for (int rg = 0; rg < 4; ++rg) o[mt][nt][rg] = 0.f;
    }

    const int ktmax = 2 * qt + 1;
    for (int kt = 0; kt <= ktmax; ++kt) {
        const int k0 = kt * 64;

        // prefetch K/V into registers (overlaps the barrier wait)
        float4 kx[4], vx[4];
#pragma unroll
        for (int l = 0; l < 4; ++l) {
            int i = tid + l * 256;
            int r = i >> 4, d4 = (i & 15) * 4;
            kx[l] = *(const float4*)(kb + (size_t)(k0 + r) * rs + d4);
            vx[l] = *(const float4*)(vb + (size_t)(k0 + r) * rs + d4);
        }
        __syncthreads();   // prev-tile PV reads done; Q visible on first iter

        // ---- store K (hi+res, B-layout) and V^T (single, B-layout+skew) ----
#pragma unroll
        for (int l = 0; l < 4; ++l) {
            int i = tid + l * 256;
            int r = i >> 4, d4 = (i & 15) * 4;
            float kv[4] = {kx[l].x, kx[l].y, kx[l].z, kx[l].w};
            float vv[4] = {vx[l].x, vx[l].y, vx[l].z, vx[l].w};
            int nt = r >> 3, n = r & 7, ks = d4 >> 3, ch = (d4 & 7) >> 2;
            int kbase = ((nt * 8 + ks) * 32 + n * 4) * 2 + ch;
            int rotK = ((n >> 2) + 2 * ((d4 >> 3) & 1)) & 3;
            int ntv = d4 >> 3, ksv = r >> 3, kk = r & 7;
            int vbase = ((ntv * 8 + ksv) * 32 + (d4 & 7) * 4 + (kk & 3)) * 2
                      + (kk >> 2) + ntv * 2;
            int rotV = (d4 >> 2) & 3;
#pragma unroll
            for (int rho = 0; rho < 4; ++rho) {
                int jk = (rho + rotK) & 3;
                float valk = pick4(kv, jk);
                uint32_t hi = f2tf32(valk);
                KP[kbase + jk * 2] = hi;
                KR[kbase + jk * 2] = f2tf32(valk - __uint_as_float(hi));
                int jv = (rho + rotV) & 3;
                VT[vbase + jv * 8] = f2tf32(pick4(vv, jv));
            }
        }
        __syncthreads();

        // ---- S = Q K^T (3-mma split) ----
        float s[2][4][4];
#pragma unroll
        for (int mt = 0; mt < 2; ++mt)
#pragma unroll
            for (int nt = 0; nt < 4; ++nt)
#pragma unroll
                for (int rg = 0; rg < 4; ++rg) s[mt][nt][rg] = 0.f;

#pragma unroll
        for (int ks = 0; ks < 8; ++ks) {
            uint4 aH[2], aR[2];
#pragma unroll
            for (int mt = 0; mt < 2; ++mt) {
                int mtg = wm * 2 + mt;
                aH[mt] = ((const uint4*)QH)[(mtg * 8 + ks) * 32 + lane];
                aR[mt] = ((const uint4*)QR)[(mtg * 8 + ks) * 32 + lane];
            }
#pragma unroll
            for (int nt = 0; nt < 4; ++nt) {
                int ntg = wn * 4 + nt;
                uint2 bH = ((const uint2*)KP)[(ntg * 8 + ks) * 32 + lane];
                uint2 bR = ((const uint2*)KR)[(ntg * 8 + ks) * 32 + lane];
#pragma unroll
                for (int mt = 0; mt < 2; ++mt) {
                    MMA_TF32(s[mt][nt], aH[mt], bH);
                    MMA_TF32(s[mt][nt], aH[mt], bR);
                    MMA_TF32(s[mt][nt], aR[mt], bH);
                }
            }
        }

        // ---- causal mask (only last two k-tiles can cross the diagonal) ----
        if (kt >= 2 * qt) {
#pragma unroll
            for (int mt = 0; mt < 2; ++mt)
#pragma unroll
                for (int nt = 0; nt < 4; ++nt)
#pragma unroll
                    for (int rg = 0; rg < 4; ++rg) {
                        int gr = q0 + (wm * 2 + mt) * 16 + (lane >> 2) + 8 * (rg >> 1);
                        int gc = k0 + wn * 32 + nt * 8 + 2 * (lane & 3) + (rg & 1);
                        if (gc > gr) s[mt][nt][rg] = -1e30f;
                    }
        }

        // ---- row max: local -> quad shfl -> cross-warp-pair via smem ----
        float pm[2][2];
#pragma unroll
        for (int mt = 0; mt < 2; ++mt) {
            pm[mt][0] = -1e30f; pm[mt][1] = -1e30f;
#pragma unroll
            for (int nt = 0; nt < 4; ++nt) {
                pm[mt][0] = fmaxf(pm[mt][0], fmaxf(s[mt][nt][0], s[mt][nt][1]));
                pm[mt][1] = fmaxf(pm[mt][1], fmaxf(s[mt][nt][2], s[mt][nt][3]));
            }
#pragma unroll
            for (int off = 1; off < 4; off <<= 1) {
                pm[mt][0] = fmaxf(pm[mt][0], __shfl_xor_sync(0xffffffffu, pm[mt][0], off));
                pm[mt][1] = fmaxf(pm[mt][1], __shfl_xor_sync(0xffffffffu, pm[mt][1], off));
            }
        }
        if ((lane & 3) == 0) {
#pragma unroll
            for (int mt = 0; mt < 2; ++mt)
#pragma unroll
                for (int rh = 0; rh < 2; ++rh)
                    smax[wn * 128 + wm * 32 + mt * 16 + rh * 8 + (lane >> 2)] = pm[mt][rh];
        }
        __syncthreads();   // smax visible; all warps done reading K fragments

        float mn[2][2], sc[2][2];
#pragma unroll
        for (int mt = 0; mt < 2; ++mt)
#pragma unroll
            for (int rh = 0; rh < 2; ++rh) {
                int row = wm * 32 + mt * 16 + rh * 8 + (lane >> 2);
                float mtile = fmaxf(smax[row], smax[128 + row]);
                mn[mt][rh] = fmaxf(m_i[mt][rh], mtile);
                sc[mt][rh] = __expf(m_i[mt][rh] - mn[mt][rh]);
                m_i[mt][rh] = mn[mt][rh];
                l_i[mt][rh] *= sc[mt][rh];
            }
#pragma unroll
        for (int mt = 0; mt < 2; ++mt)
#pragma unroll
            for (int nt = 0; nt < 4; ++nt) {
                o[mt][nt][0] *= sc[mt][0]; o[mt][nt][1] *= sc[mt][0];
                o[mt][nt][2] *= sc[mt][1]; o[mt][nt][3] *= sc[mt][1];
            }

        // ---- p = exp(s - m); store P single tf32 (A-layout into KP) ----
        float ps[2][2] = {{0.f, 0.f}, {0.f, 0.f}};
        const int rotP = lane & 3;
#pragma unroll
        for (int mt = 0; mt < 2; ++mt) {
            int mtg = wm * 2 + mt;
#pragma unroll
            for (int nt = 0; nt < 4; ++nt) {
                float p4[4];
#pragma unroll
                for (int rg = 0; rg < 4; ++rg) {
                    p4[rg] = __expf(s[mt][nt][rg] - mn[mt][rg >> 1]);
                    ps[mt][rg >> 1] += p4[rg];
                }
                int ksp = wn * 4 + nt;
#pragma unroll
                for (int rho = 0; rho < 4; ++rho) {
                    int rg = (rho + rotP) & 3;
                    int idx = ((mtg * 8 + ksp) * 32 + (lane >> 2) * 4
                               + 2 * (lane & 1) + (rg & 1)) * 4
                            + (rg >> 1) + 2 * ((lane >> 1) & 1);
                    KP[idx] = f2tf32(pick4(p4, rg));
                }
            }
        }
#pragma unroll
        for (int mt = 0; mt < 2; ++mt)
#pragma unroll
            for (int off = 1; off < 4; off <<= 1) {
                ps[mt][0] += __shfl_xor_sync(0xffffffffu, ps[mt][0], off);
                ps[mt][1] += __shfl_xor_sync(0xffffffffu, ps[mt][1], off);
            }
        if ((lane & 3) == 0) {
#pragma unroll
            for (int mt = 0; mt < 2; ++mt)
#pragma unroll
                for (int rh = 0; rh < 2; ++rh)
                    ssum[wn * 128 + wm * 32 + mt * 16 + rh * 8 + (lane >> 2)] = ps[mt][rh];
        }
        __syncthreads();   // P + ssum visible

#pragma unroll
        for (int mt = 0; mt < 2; ++mt)
#pragma unroll
            for (int rh = 0; rh < 2; ++rh) {
                int row = wm * 32 + mt * 16 + rh * 8 + (lane >> 2);
                l_i[mt][rh] += ssum[row] + ssum[128 + row];
            }

        // ---- O += P V (single mma) ----
#pragma unroll
        for (int ks = 0; ks < 8; ++ks) {
            uint4 aP[2];
#pragma unroll
            for (int mt = 0; mt < 2; ++mt)
                aP[mt] = ((const uint4*)KP)[((wm * 2 + mt) * 8 + ks) * 32 + lane];
#pragma unroll
            for (int nt = 0; nt < 4; ++nt) {
                int ntg = wn * 4 + nt;
                uint2 bV = ((const uint2*)VT)[(ntg * 8 + ks) * 32 + lane + ntg];
#pragma unroll
                for (int mt = 0; mt < 2; ++mt)
                    MMA_TF32(o[mt][nt], aP[mt], bV);
            }
        }
    }

    // ---- epilogue: O / l ----
    float* yb = y + (size_t)b * TFULL * CDIM + (size_t)h * HDIM;
#pragma unroll
    for (int mt = 0; mt < 2; ++mt) {
        float inv0 = 1.f / l_i[mt][0];
        float inv1 = 1.f / l_i[mt][1];
        int gr0 = q0 + (wm * 2 + mt) * 16 + (lane >> 2);
#pragma unroll
        for (int nt = 0; nt < 4; ++nt) {
            int col = wn * 32 + nt * 8 + 2 * (lane & 3);
            *(float2*)(yb + (size_t)gr0 * CDIM + col) =
                make_float2(o[mt][nt][0] * inv0, o[mt][nt][1] * inv0);
            *(float2*)(yb + (size_t)(gr0 + 8) * CDIM + col) =
                make_float2(o[mt][nt][2] * inv1, o[mt][nt][3] * inv1);
        }
    }
}

// ---------------------------------------------------------------------------
extern "C" void kernel_launch(void* const* d_in, const int* in_sizes, int n_in,
                              void* d_out, int out_size)
{
    const float* x      = (const float*)d_in[0];   // (B,T,C)
    const float* w_attn = (const float*)d_in[1];   // (3C,C)
    const float* w_proj = (const float*)d_in[2];   // (C,C)
    float* out = (float*)d_out;                    // (B,T,C)

    float* qkv = nullptr;
    float* yb  = nullptr;
    cudaGetSymbolAddress((void**)&qkv, g_qkv);
    cudaGetSymbolAddress((void**)&yb, g_y);

    const int M = BATCH * TFULL;              // 8192
    const int ATTN_SMEM = 29312 * 4;          // 117248 bytes

    cudaFuncSetAttribute(flash_attn_tc2,
                         cudaFuncAttributeMaxDynamicSharedMemorySize, ATTN_SMEM);

    // 1) qkv = x @ w_attn^T   : (8192 x 3072)
    gemm_nt_tc<<<dim3(3 * CDIM / 128, M / 128), 256>>>(x, w_attn, qkv, M, 3 * CDIM, CDIM);

    // 2) y = causal_attention(qkv), q-tile 128
    flash_attn_tc2<<<dim3(TFULL / 128, BATCH * NHEAD), 256, ATTN_SMEM>>>(qkv, yb);

    // 3) out = y @ w_proj^T   : (8192 x 1024)
    gemm_nt_tc<<<dim3(CDIM / 128, M / 128), 256>>>(yb, w_proj, out, M, CDIM, CDIM);
}